// round 1
// baseline (speedup 1.0000x reference)
#include <cuda_runtime.h>

#define NUSR 100000
#define NITM 50000
#define NNODE (NUSR + NITM)
#define DD 128
#define EE 1500000
#define HALFD 64
#define KCAT 320

// -------- scratch (device globals: allocation-free) --------
__device__ float g_bufA[(size_t)NNODE * DD];
__device__ float g_bufB[(size_t)NNODE * DD];
__device__ float g_bufC[(size_t)NNODE * DD];
__device__ float g_cat [(size_t)NNODE * KCAT];
__device__ float g_invdeg[NNODE];

// -------- utility: zero --------
__global__ void zero_kernel(float4* __restrict__ p, int n4) {
    int i = blockIdx.x * blockDim.x + threadIdx.x;
    int st = gridDim.x * blockDim.x;
    for (; i < n4; i += st) p[i] = make_float4(0.f, 0.f, 0.f, 0.f);
}

// -------- degree --------
__global__ void deg_kernel(const int* __restrict__ dst) {
    int i = blockIdx.x * blockDim.x + threadIdx.x;
    if (i < EE) atomicAdd(&g_invdeg[dst[i]], 1.0f);
}

__global__ void invdeg_kernel() {
    int i = blockIdx.x * blockDim.x + threadIdx.x;
    if (i < NNODE) g_invdeg[i] = 1.0f / fmaxf(g_invdeg[i], 1.0f);
}

// -------- embedding gather: build g_cat[n, 320] = [feat_mean(128) | text_mean(3*64)] --------
__global__ void embed_kernel(const int* __restrict__ uf,  const int* __restrict__ itf,
                             const int* __restrict__ ut,  const int* __restrict__ it,
                             const float* __restrict__ ufe, const float* __restrict__ ife,
                             const float* __restrict__ we) {
    int gw   = (blockIdx.x * blockDim.x + threadIdx.x) >> 5;
    int lane = threadIdx.x & 31;
    if (gw >= NNODE) return;
    int n = gw;
    bool user = n < NUSR;
    const int*   f   = user ? uf + (size_t)n * 10 : itf + (size_t)(n - NUSR) * 10;
    const float* tab = user ? ufe : ife;

    float a0 = 0.f, a1 = 0.f, a2 = 0.f, a3 = 0.f;
#pragma unroll
    for (int j = 0; j < 10; j++) {
        int r = __ldg(f + j);
        const float* tr = tab + (size_t)r * DD + lane;
        a0 += __ldg(tr);      a1 += __ldg(tr + 32);
        a2 += __ldg(tr + 64); a3 += __ldg(tr + 96);
    }
    float* catrow = g_cat + (size_t)n * KCAT;
    catrow[lane]      = a0 * 0.1f;
    catrow[lane + 32] = a1 * 0.1f;
    catrow[lane + 64] = a2 * 0.1f;
    catrow[lane + 96] = a3 * 0.1f;

    const int* t = user ? ut + (size_t)n * 24 : it + (size_t)(n - NUSR) * 24;
#pragma unroll
    for (int fl = 0; fl < 3; fl++) {
        float b0 = 0.f, b1 = 0.f;
#pragma unroll
        for (int w = 0; w < 8; w++) {
            int r = __ldg(t + fl * 8 + w);
            const float* wr = we + (size_t)r * HALFD + lane;
            b0 += __ldg(wr);
            b1 += __ldg(wr + 32);
        }
        catrow[128 + fl * 64 + lane]      = b0 * 0.125f;
        catrow[128 + fl * 64 + lane + 32] = b1 * 0.125f;
    }
}

// -------- edge scatter: agg[dst] += x[src]  (warp per edge, float4 loads, 4 atomics/lane) --------
__global__ void scatter_kernel(const int* __restrict__ src, const int* __restrict__ dst,
                               const float* __restrict__ x, float* __restrict__ agg) {
    int gw   = (blockIdx.x * blockDim.x + threadIdx.x) >> 5;
    int lane = threadIdx.x & 31;
    if (gw >= EE) return;
    int s = __ldg(src + gw);
    int d = __ldg(dst + gw);
    float4 v = __ldg((const float4*)(x + (size_t)s * DD) + lane);
    float* a = agg + (size_t)d * DD + lane * 4;
    atomicAdd(a + 0, v.x);
    atomicAdd(a + 1, v.y);
    atomicAdd(a + 2, v.z);
    atomicAdd(a + 3, v.w);
}

// -------- fp32 GEMM: out[M,128] = [A | A2] @ W[K1+K2,128] + bias (+addmat) (row-scale A) --------
// 128x128 tile, BK=16, 256 threads, 8x8 microtile per thread.
template <bool RELU>
__global__ __launch_bounds__(256) void gemm128(
    const float* __restrict__ A,  int K1,
    const float* __restrict__ A2, int K2,
    const float* __restrict__ W,
    const float* __restrict__ bias,
    const float* __restrict__ addmat,
    const float* __restrict__ rowscale,
    float* __restrict__ out, int M)
{
    __shared__ float As[16][128];
    __shared__ float Ws[16][128];
    int tid = threadIdx.x;
    int tx = tid & 15, ty = tid >> 4;
    int r0 = blockIdx.x * 128;

    float acc[8][8];
#pragma unroll
    for (int i = 0; i < 8; i++)
#pragma unroll
        for (int j = 0; j < 8; j++) acc[i][j] = 0.f;

    int K = K1 + K2;
    for (int kt = 0; kt < K; kt += 16) {
        const float* Ab; int stride, kk;
        if (kt < K1) { Ab = A;  stride = K1; kk = kt; }
        else         { Ab = A2; stride = K2; kk = kt - K1; }

        // load A tile (transposed into smem)
#pragma unroll
        for (int l = 0; l < 2; l++) {
            int idx = tid + l * 256;
            int m = idx >> 2, kq = (idx & 3) * 4;
            int row = r0 + m;
            float4 v = make_float4(0.f, 0.f, 0.f, 0.f);
            if (row < M) {
                v = *(const float4*)(Ab + (size_t)row * stride + kk + kq);
                if (rowscale) {
                    float s = rowscale[row];
                    v.x *= s; v.y *= s; v.z *= s; v.w *= s;
                }
            }
            As[kq + 0][m] = v.x;
            As[kq + 1][m] = v.y;
            As[kq + 2][m] = v.z;
            As[kq + 3][m] = v.w;
        }
        // load W tile
#pragma unroll
        for (int l = 0; l < 2; l++) {
            int idx = tid + l * 256;
            int k = idx >> 5, nq = (idx & 31) * 4;
            *(float4*)&Ws[k][nq] = *(const float4*)(W + (size_t)(kt + k) * 128 + nq);
        }
        __syncthreads();

#pragma unroll
        for (int k = 0; k < 16; k++) {
            float ra[8], rb[8];
            *(float4*)&ra[0] = *(const float4*)&As[k][ty * 8];
            *(float4*)&ra[4] = *(const float4*)&As[k][ty * 8 + 4];
            *(float4*)&rb[0] = *(const float4*)&Ws[k][tx * 4];
            *(float4*)&rb[4] = *(const float4*)&Ws[k][64 + tx * 4];
#pragma unroll
            for (int i = 0; i < 8; i++)
#pragma unroll
                for (int j = 0; j < 8; j++)
                    acc[i][j] += ra[i] * rb[j];
        }
        __syncthreads();
    }

    // epilogue
#pragma unroll
    for (int i = 0; i < 8; i++) {
        int row = r0 + ty * 8 + i;
        if (row >= M) continue;
#pragma unroll
        for (int half = 0; half < 2; half++) {
            int col = half * 64 + tx * 4;
            float4 v;
            float* vp = &v.x;
#pragma unroll
            for (int u = 0; u < 4; u++) {
                float c = acc[i][half * 4 + u] + bias[col + u];
                if (addmat) c += addmat[(size_t)row * 128 + col + u];
                if (RELU) c = fmaxf(c, 0.f);
                vp[u] = c;
            }
            *(float4*)(out + (size_t)row * 128 + col) = v;
        }
    }
}

// -------- launch --------
extern "C" void kernel_launch(void* const* d_in, const int* in_sizes, int n_in,
                              void* d_out, int out_size) {
    const int*   edge          = (const int*)d_in[0];
    const int*   src           = edge;
    const int*   dstp          = edge + EE;
    const int*   user_features = (const int*)d_in[1];
    const int*   item_features = (const int*)d_in[2];
    const int*   user_text     = (const int*)d_in[3];
    const int*   item_text     = (const int*)d_in[4];
    const float* user_id_emb   = (const float*)d_in[5];
    const float* item_id_emb   = (const float*)d_in[6];
    const float* user_feat_emb = (const float*)d_in[7];
    const float* item_feat_emb = (const float*)d_in[8];
    const float* word_emb      = (const float*)d_in[9];
    const float* user_projW    = (const float*)d_in[10];
    const float* user_projb    = (const float*)d_in[11];
    const float* item_projW    = (const float*)d_in[12];
    const float* item_projb    = (const float*)d_in[13];
    const float* w0W = (const float*)d_in[14];
    const float* w0b = (const float*)d_in[15];
    const float* w1W = (const float*)d_in[16];
    const float* w1b = (const float*)d_in[17];
    const float* v0W = (const float*)d_in[18];
    const float* v0b = (const float*)d_in[19];
    const float* v1W = (const float*)d_in[20];
    const float* v1b = (const float*)d_in[21];

    float *pA, *pB, *pC, *pcat, *pinv;
    cudaGetSymbolAddress((void**)&pA,   g_bufA);
    cudaGetSymbolAddress((void**)&pB,   g_bufB);
    cudaGetSymbolAddress((void**)&pC,   g_bufC);
    cudaGetSymbolAddress((void**)&pcat, g_cat);
    cudaGetSymbolAddress((void**)&pinv, g_invdeg);

    const int ZB = 2048;
    // degrees
    zero_kernel<<<64, 256>>>((float4*)pinv, NNODE / 4);
    deg_kernel<<<(EE + 255) / 256, 256>>>(dstp);
    invdeg_kernel<<<(NNODE + 255) / 256, 256>>>();

    // node features -> g_cat
    embed_kernel<<<(NNODE * 32 + 255) / 256, 256>>>(
        user_features, item_features, user_text, item_text,
        user_feat_emb, item_feat_emb, word_emb);

    // projection (+id_emb) -> x in bufA
    gemm128<false><<<(NUSR + 127) / 128, 256>>>(
        pcat, KCAT, nullptr, 0, user_projW, user_projb, user_id_emb, nullptr, pA, NUSR);
    gemm128<false><<<(NITM + 127) / 128, 256>>>(
        pcat + (size_t)NUSR * KCAT, KCAT, nullptr, 0, item_projW, item_projb, item_id_emb,
        nullptr, pA + (size_t)NUSR * DD, NITM);

    // ----- layer 0 -----
    zero_kernel<<<ZB, 256>>>((float4*)pB, NNODE * DD / 4);
    scatter_kernel<<<(EE * 32 + 255) / 256, 256>>>(src, dstp, pA, pB);
    // h = relu((agg/deg) @ v0 + b)  -> bufC
    gemm128<true><<<(NNODE + 127) / 128, 256>>>(
        pB, DD, nullptr, 0, v0W, v0b, nullptr, pinv, pC, NNODE);
    // x1 = relu([x,h] @ w0 + b) -> bufB
    gemm128<true><<<(NNODE + 127) / 128, 256>>>(
        pA, DD, pC, DD, w0W, w0b, nullptr, nullptr, pB, NNODE);

    // ----- layer 1 -----
    zero_kernel<<<ZB, 256>>>((float4*)pA, NNODE * DD / 4);
    scatter_kernel<<<(EE * 32 + 255) / 256, 256>>>(src, dstp, pB, pA);
    gemm128<true><<<(NNODE + 127) / 128, 256>>>(
        pA, DD, nullptr, 0, v1W, v1b, nullptr, pinv, pC, NNODE);
    gemm128<false><<<(NNODE + 127) / 128, 256>>>(
        pB, DD, pC, DD, w1W, w1b, nullptr, nullptr, (float*)d_out, NNODE);
}

// round 2
// speedup vs baseline: 1.1904x; 1.1904x over previous
#include <cuda_runtime.h>
#include <cstdint>

#define NUSR 100000
#define NITM 50000
#define NNODE (NUSR + NITM)
#define DD 128
#define EE 1500000
#define HALFD 64
#define KCAT 320

// -------- scratch (device globals: allocation-free) --------
__device__ float g_bufA[(size_t)NNODE * DD];
__device__ float g_bufB[(size_t)NNODE * DD];
__device__ float g_bufC[(size_t)NNODE * DD];
__device__ float g_cat [(size_t)NNODE * KCAT];
__device__ float g_invdeg[NNODE];

// -------- utility: zero --------
__global__ void zero_kernel(float4* __restrict__ p, int n4) {
    int i = blockIdx.x * blockDim.x + threadIdx.x;
    int st = gridDim.x * blockDim.x;
    for (; i < n4; i += st) p[i] = make_float4(0.f, 0.f, 0.f, 0.f);
}

// -------- degree --------
__global__ void deg_kernel(const int* __restrict__ dst) {
    int i = blockIdx.x * blockDim.x + threadIdx.x;
    if (i < EE) atomicAdd(&g_invdeg[dst[i]], 1.0f);
}

__global__ void invdeg_kernel() {
    int i = blockIdx.x * blockDim.x + threadIdx.x;
    if (i < NNODE) g_invdeg[i] = 1.0f / fmaxf(g_invdeg[i], 1.0f);
}

// -------- embedding gather: g_cat[n,320] = [feat_mean(128) | text_mean(3*64)] --------
__global__ void embed_kernel(const int* __restrict__ uf,  const int* __restrict__ itf,
                             const int* __restrict__ ut,  const int* __restrict__ it,
                             const float* __restrict__ ufe, const float* __restrict__ ife,
                             const float* __restrict__ we) {
    int gw   = (blockIdx.x * blockDim.x + threadIdx.x) >> 5;
    int lane = threadIdx.x & 31;
    if (gw >= NNODE) return;
    int n = gw;
    bool user = n < NUSR;
    const int*   f   = user ? uf + (size_t)n * 10 : itf + (size_t)(n - NUSR) * 10;
    const float* tab = user ? ufe : ife;

    float a0 = 0.f, a1 = 0.f, a2 = 0.f, a3 = 0.f;
#pragma unroll
    for (int j = 0; j < 10; j++) {
        int r = __ldg(f + j);
        const float* tr = tab + (size_t)r * DD + lane;
        a0 += __ldg(tr);      a1 += __ldg(tr + 32);
        a2 += __ldg(tr + 64); a3 += __ldg(tr + 96);
    }
    float* catrow = g_cat + (size_t)n * KCAT;
    catrow[lane]      = a0 * 0.1f;
    catrow[lane + 32] = a1 * 0.1f;
    catrow[lane + 64] = a2 * 0.1f;
    catrow[lane + 96] = a3 * 0.1f;

    const int* t = user ? ut + (size_t)n * 24 : it + (size_t)(n - NUSR) * 24;
#pragma unroll
    for (int fl = 0; fl < 3; fl++) {
        float b0 = 0.f, b1 = 0.f;
#pragma unroll
        for (int w = 0; w < 8; w++) {
            int r = __ldg(t + fl * 8 + w);
            const float* wr = we + (size_t)r * HALFD + lane;
            b0 += __ldg(wr);
            b1 += __ldg(wr + 32);
        }
        catrow[128 + fl * 64 + lane]      = b0 * 0.125f;
        catrow[128 + fl * 64 + lane + 32] = b1 * 0.125f;
    }
}

// -------- edge scatter: agg[dst] += x[src] (warp per edge) --------
__global__ void scatter_kernel(const int* __restrict__ src, const int* __restrict__ dst,
                               const float* __restrict__ x, float* __restrict__ agg) {
    int gw   = (blockIdx.x * blockDim.x + threadIdx.x) >> 5;
    int lane = threadIdx.x & 31;
    if (gw >= EE) return;
    int s = __ldg(src + gw);
    int d = __ldg(dst + gw);
    float4 v = __ldg((const float4*)(x + (size_t)s * DD) + lane);
    float* a = agg + (size_t)d * DD + lane * 4;
    atomicAdd(a + 0, v.x);
    atomicAdd(a + 1, v.y);
    atomicAdd(a + 2, v.z);
    atomicAdd(a + 3, v.w);
}

// -------- tf32 conversion helper --------
__device__ __forceinline__ uint32_t f2tf32(float v) {
    uint32_t r;
    asm("cvt.rna.tf32.f32 %0, %1;" : "=r"(r) : "f"(v));
    return r;
}

__device__ __forceinline__ void mma_tf32(float* c, const uint32_t* a, const uint32_t* b) {
    asm volatile(
        "mma.sync.aligned.m16n8k8.row.col.f32.tf32.tf32.f32 "
        "{%0,%1,%2,%3}, {%4,%5,%6,%7}, {%8,%9}, {%0,%1,%2,%3};"
        : "+f"(c[0]), "+f"(c[1]), "+f"(c[2]), "+f"(c[3])
        : "r"(a[0]), "r"(a[1]), "r"(a[2]), "r"(a[3]), "r"(b[0]), "r"(b[1]));
}

// -------- TF32 tensor-core GEMM: out[M,128] = [A|A2] @ W[K1+K2,128] + bias (+addmat) --------
// 128x128 block tile, BK=16, 256 threads (8 warps, 64x32 warp tiles), fp32 accum.
template <bool RELU>
__global__ __launch_bounds__(256) void gemm_tf32(
    const float* __restrict__ A,  int K1,
    const float* __restrict__ A2, int K2,
    const float* __restrict__ W,
    const float* __restrict__ bias,
    const float* __restrict__ addmat,
    const float* __restrict__ rowscale,
    float* __restrict__ out, int M)
{
    __shared__ uint32_t As[128][17];   // [row][k] + pad
    __shared__ uint32_t Ws[16][132];   // [k][n] + pad

    int tid  = threadIdx.x;
    int lane = tid & 31;
    int wid  = tid >> 5;
    int wm = wid & 1;          // 0/1 : which 64-row half
    int wn = wid >> 1;         // 0..3: which 32-col quarter
    int g  = lane >> 2;        // group id (0..7)
    int tg = lane & 3;         // thread in group (0..3)
    int r0 = blockIdx.x * 128;

    float acc[4][4][4];
#pragma unroll
    for (int mt = 0; mt < 4; mt++)
#pragma unroll
        for (int nt = 0; nt < 4; nt++)
#pragma unroll
            for (int u = 0; u < 4; u++) acc[mt][nt][u] = 0.f;

    int K = K1 + K2;
    for (int kt = 0; kt < K; kt += 16) {
        const float* Ab; int stride, kk;
        if (kt < K1) { Ab = A;  stride = K1; kk = kt; }
        else         { Ab = A2; stride = K2; kk = kt - K1; }

        // stage A tile: 128 rows x 16 k  (each thread: 2x float4)
#pragma unroll
        for (int l = 0; l < 2; l++) {
            int idx = tid + l * 256;
            int m = idx >> 2, c4 = (idx & 3) * 4;
            int row = r0 + m;
            float4 v = make_float4(0.f, 0.f, 0.f, 0.f);
            if (row < M) {
                v = *(const float4*)(Ab + (size_t)row * stride + kk + c4);
                if (rowscale) {
                    float s = rowscale[row];
                    v.x *= s; v.y *= s; v.z *= s; v.w *= s;
                }
            }
            As[m][c4 + 0] = f2tf32(v.x);
            As[m][c4 + 1] = f2tf32(v.y);
            As[m][c4 + 2] = f2tf32(v.z);
            As[m][c4 + 3] = f2tf32(v.w);
        }
        // stage W tile: 16 k x 128 n
#pragma unroll
        for (int l = 0; l < 2; l++) {
            int idx = tid + l * 256;
            int k = idx >> 5, n4 = (idx & 31) * 4;
            float4 v = *(const float4*)(W + (size_t)(kt + k) * 128 + n4);
            Ws[k][n4 + 0] = f2tf32(v.x);
            Ws[k][n4 + 1] = f2tf32(v.y);
            Ws[k][n4 + 2] = f2tf32(v.z);
            Ws[k][n4 + 3] = f2tf32(v.w);
        }
        __syncthreads();

#pragma unroll
        for (int ks = 0; ks < 16; ks += 8) {
            uint32_t afr[4][4];
#pragma unroll
            for (int mt = 0; mt < 4; mt++) {
                int rb = wm * 64 + mt * 16 + g;
                afr[mt][0] = As[rb    ][ks + tg];
                afr[mt][1] = As[rb + 8][ks + tg];
                afr[mt][2] = As[rb    ][ks + tg + 4];
                afr[mt][3] = As[rb + 8][ks + tg + 4];
            }
            uint32_t bfr[4][2];
#pragma unroll
            for (int nt = 0; nt < 4; nt++) {
                int cb = wn * 32 + nt * 8 + g;
                bfr[nt][0] = Ws[ks + tg    ][cb];
                bfr[nt][1] = Ws[ks + tg + 4][cb];
            }
#pragma unroll
            for (int mt = 0; mt < 4; mt++)
#pragma unroll
                for (int nt = 0; nt < 4; nt++)
                    mma_tf32(acc[mt][nt], afr[mt], bfr[nt]);
        }
        __syncthreads();
    }

    // epilogue: c0,c1 @ (row=g, col=2tg,2tg+1); c2,c3 @ row=g+8
#pragma unroll
    for (int mt = 0; mt < 4; mt++) {
#pragma unroll
        for (int nt = 0; nt < 4; nt++) {
            int col = wn * 32 + nt * 8 + tg * 2;
            int rowa = r0 + wm * 64 + mt * 16 + g;
            int rowb = rowa + 8;
            float b0 = bias[col], b1 = bias[col + 1];
            if (rowa < M) {
                float x0 = acc[mt][nt][0] + b0;
                float x1 = acc[mt][nt][1] + b1;
                if (addmat) {
                    x0 += addmat[(size_t)rowa * 128 + col];
                    x1 += addmat[(size_t)rowa * 128 + col + 1];
                }
                if (RELU) { x0 = fmaxf(x0, 0.f); x1 = fmaxf(x1, 0.f); }
                *(float2*)(out + (size_t)rowa * 128 + col) = make_float2(x0, x1);
            }
            if (rowb < M) {
                float x2 = acc[mt][nt][2] + b0;
                float x3 = acc[mt][nt][3] + b1;
                if (addmat) {
                    x2 += addmat[(size_t)rowb * 128 + col];
                    x3 += addmat[(size_t)rowb * 128 + col + 1];
                }
                if (RELU) { x2 = fmaxf(x2, 0.f); x3 = fmaxf(x3, 0.f); }
                *(float2*)(out + (size_t)rowb * 128 + col) = make_float2(x2, x3);
            }
        }
    }
}

// -------- launch --------
extern "C" void kernel_launch(void* const* d_in, const int* in_sizes, int n_in,
                              void* d_out, int out_size) {
    const int*   edge          = (const int*)d_in[0];
    const int*   src           = edge;
    const int*   dstp          = edge + EE;
    const int*   user_features = (const int*)d_in[1];
    const int*   item_features = (const int*)d_in[2];
    const int*   user_text     = (const int*)d_in[3];
    const int*   item_text     = (const int*)d_in[4];
    const float* user_id_emb   = (const float*)d_in[5];
    const float* item_id_emb   = (const float*)d_in[6];
    const float* user_feat_emb = (const float*)d_in[7];
    const float* item_feat_emb = (const float*)d_in[8];
    const float* word_emb      = (const float*)d_in[9];
    const float* user_projW    = (const float*)d_in[10];
    const float* user_projb    = (const float*)d_in[11];
    const float* item_projW    = (const float*)d_in[12];
    const float* item_projb    = (const float*)d_in[13];
    const float* w0W = (const float*)d_in[14];
    const float* w0b = (const float*)d_in[15];
    const float* w1W = (const float*)d_in[16];
    const float* w1b = (const float*)d_in[17];
    const float* v0W = (const float*)d_in[18];
    const float* v0b = (const float*)d_in[19];
    const float* v1W = (const float*)d_in[20];
    const float* v1b = (const float*)d_in[21];

    float *pA, *pB, *pC, *pcat, *pinv;
    cudaGetSymbolAddress((void**)&pA,   g_bufA);
    cudaGetSymbolAddress((void**)&pB,   g_bufB);
    cudaGetSymbolAddress((void**)&pC,   g_bufC);
    cudaGetSymbolAddress((void**)&pcat, g_cat);
    cudaGetSymbolAddress((void**)&pinv, g_invdeg);

    const int ZB = 2048;
    // degrees
    zero_kernel<<<64, 256>>>((float4*)pinv, NNODE / 4);
    deg_kernel<<<(EE + 255) / 256, 256>>>(dstp);
    invdeg_kernel<<<(NNODE + 255) / 256, 256>>>();

    // node features -> g_cat
    embed_kernel<<<(NNODE * 32 + 255) / 256, 256>>>(
        user_features, item_features, user_text, item_text,
        user_feat_emb, item_feat_emb, word_emb);

    // projection (+id_emb) -> x in bufA
    gemm_tf32<false><<<(NUSR + 127) / 128, 256>>>(
        pcat, KCAT, nullptr, 0, user_projW, user_projb, user_id_emb, nullptr, pA, NUSR);
    gemm_tf32<false><<<(NITM + 127) / 128, 256>>>(
        pcat + (size_t)NUSR * KCAT, KCAT, nullptr, 0, item_projW, item_projb, item_id_emb,
        nullptr, pA + (size_t)NUSR * DD, NITM);

    // ----- layer 0 -----
    zero_kernel<<<ZB, 256>>>((float4*)pB, NNODE * DD / 4);
    scatter_kernel<<<(EE * 32 + 255) / 256, 256>>>(src, dstp, pA, pB);
    gemm_tf32<true><<<(NNODE + 127) / 128, 256>>>(
        pB, DD, nullptr, 0, v0W, v0b, nullptr, pinv, pC, NNODE);
    gemm_tf32<true><<<(NNODE + 127) / 128, 256>>>(
        pA, DD, pC, DD, w0W, w0b, nullptr, nullptr, pB, NNODE);

    // ----- layer 1 -----
    zero_kernel<<<ZB, 256>>>((float4*)pA, NNODE * DD / 4);
    scatter_kernel<<<(EE * 32 + 255) / 256, 256>>>(src, dstp, pB, pA);
    gemm_tf32<true><<<(NNODE + 127) / 128, 256>>>(
        pA, DD, nullptr, 0, v1W, v1b, nullptr, pinv, pC, NNODE);
    gemm_tf32<false><<<(NNODE + 127) / 128, 256>>>(
        pB, DD, pC, DD, w1W, w1b, nullptr, nullptr, (float*)d_out, NNODE);
}

// round 3
// speedup vs baseline: 2.3522x; 1.9759x over previous
#include <cuda_runtime.h>
#include <cstdint>

#define NUSR 100000
#define NITM 50000
#define NNODE (NUSR + NITM)
#define DD 128
#define EE 1500000
#define HALFD 64
#define KCAT 320
#define NBLK 586   // ceil(NNODE/256)

// -------- scratch (device globals: allocation-free) --------
__device__ float g_bufA[(size_t)NNODE * DD];
__device__ float g_bufB[(size_t)NNODE * DD];
__device__ float g_bufC[(size_t)NNODE * DD];
__device__ float g_cat [(size_t)NNODE * KCAT];
__device__ float g_invdeg[NNODE];
__device__ int   g_deg[NNODE];
__device__ int   g_bsum[1024];
__device__ int   g_offs[NNODE + 1];
__device__ int   g_cursor[NNODE];
__device__ int   g_csr[EE];

// -------- utility: zero --------
__global__ void zero_kernel(uint4* __restrict__ p, int n4) {
    int i = blockIdx.x * blockDim.x + threadIdx.x;
    int st = gridDim.x * blockDim.x;
    for (; i < n4; i += st) p[i] = make_uint4(0, 0, 0, 0);
}

// -------- degree count (int) --------
__global__ void deg_kernel(const int* __restrict__ dst) {
    int i = blockIdx.x * blockDim.x + threadIdx.x;
    if (i < EE) atomicAdd(&g_deg[dst[i]], 1);
}

__global__ void invdeg_kernel() {
    int i = blockIdx.x * blockDim.x + threadIdx.x;
    if (i < NNODE) g_invdeg[i] = 1.0f / fmaxf((float)g_deg[i], 1.0f);
}

// -------- scan phase 1: per-block exclusive scan of degrees --------
__global__ void scan1_kernel() {
    __shared__ int sm[256];
    int tid = threadIdx.x;
    int i = blockIdx.x * 256 + tid;
    int v = (i < NNODE) ? g_deg[i] : 0;
    sm[tid] = v;
    __syncthreads();
#pragma unroll
    for (int d = 1; d < 256; d <<= 1) {
        int t = (tid >= d) ? sm[tid - d] : 0;
        __syncthreads();
        sm[tid] += t;
        __syncthreads();
    }
    if (i < NNODE) g_offs[i] = sm[tid] - v;   // exclusive, block-local
    if (tid == 255) g_bsum[blockIdx.x] = sm[255];
}

// -------- scan phase 2: scan block sums (single block) --------
__global__ void scan2_kernel() {
    __shared__ int sm[1024];
    int tid = threadIdx.x;
    int v = (tid < NBLK) ? g_bsum[tid] : 0;
    sm[tid] = v;
    __syncthreads();
#pragma unroll
    for (int d = 1; d < 1024; d <<= 1) {
        int t = (tid >= d) ? sm[tid - d] : 0;
        __syncthreads();
        sm[tid] += t;
        __syncthreads();
    }
    g_bsum[tid] = sm[tid] - v;   // exclusive block base
}

// -------- scan phase 3: add block base, init cursor --------
__global__ void scan3_kernel() {
    int i = blockIdx.x * blockDim.x + threadIdx.x;
    if (i < NNODE) {
        int o = g_offs[i] + g_bsum[i >> 8];
        g_offs[i] = o;
        g_cursor[i] = o;
    }
    if (i == 0) g_offs[NNODE] = EE;
}

// -------- CSR fill --------
__global__ void fill_kernel(const int* __restrict__ src, const int* __restrict__ dst) {
    int i = blockIdx.x * blockDim.x + threadIdx.x;
    if (i < EE) {
        int d = dst[i];
        int pos = atomicAdd(&g_cursor[d], 1);
        g_csr[pos] = src[i];
    }
}

// -------- gather aggregation: out[n] = mean_{s in N(n)} x[s]   (warp per node) --------
__global__ void agg_kernel(const float* __restrict__ x, float* __restrict__ out) {
    int gw   = (blockIdx.x * blockDim.x + threadIdx.x) >> 5;
    int lane = threadIdx.x & 31;
    if (gw >= NNODE) return;
    int off = g_offs[gw];
    int end = g_offs[gw + 1];
    float4 acc = make_float4(0.f, 0.f, 0.f, 0.f);
    for (int j = off; j < end; j++) {
        int s = __ldg(&g_csr[j]);
        float4 v = __ldg((const float4*)(x + (size_t)s * DD) + lane);
        acc.x += v.x; acc.y += v.y; acc.z += v.z; acc.w += v.w;
    }
    float sc = g_invdeg[gw];
    acc.x *= sc; acc.y *= sc; acc.z *= sc; acc.w *= sc;
    *((float4*)(out + (size_t)gw * DD) + lane) = acc;
}

// -------- embedding gather: g_cat[n,320] = [feat_mean(128) | text_mean(3*64)] --------
__global__ void embed_kernel(const int* __restrict__ uf,  const int* __restrict__ itf,
                             const int* __restrict__ ut,  const int* __restrict__ it,
                             const float* __restrict__ ufe, const float* __restrict__ ife,
                             const float* __restrict__ we) {
    int gw   = (blockIdx.x * blockDim.x + threadIdx.x) >> 5;
    int lane = threadIdx.x & 31;
    if (gw >= NNODE) return;
    int n = gw;
    bool user = n < NUSR;
    const int*   f   = user ? uf + (size_t)n * 10 : itf + (size_t)(n - NUSR) * 10;
    const float* tab = user ? ufe : ife;

    float a0 = 0.f, a1 = 0.f, a2 = 0.f, a3 = 0.f;
#pragma unroll
    for (int j = 0; j < 10; j++) {
        int r = __ldg(f + j);
        const float* tr = tab + (size_t)r * DD + lane;
        a0 += __ldg(tr);      a1 += __ldg(tr + 32);
        a2 += __ldg(tr + 64); a3 += __ldg(tr + 96);
    }
    float* catrow = g_cat + (size_t)n * KCAT;
    catrow[lane]      = a0 * 0.1f;
    catrow[lane + 32] = a1 * 0.1f;
    catrow[lane + 64] = a2 * 0.1f;
    catrow[lane + 96] = a3 * 0.1f;

    const int* t = user ? ut + (size_t)n * 24 : it + (size_t)(n - NUSR) * 24;
#pragma unroll
    for (int fl = 0; fl < 3; fl++) {
        float b0 = 0.f, b1 = 0.f;
#pragma unroll
        for (int w = 0; w < 8; w++) {
            int r = __ldg(t + fl * 8 + w);
            const float* wr = we + (size_t)r * HALFD + lane;
            b0 += __ldg(wr);
            b1 += __ldg(wr + 32);
        }
        catrow[128 + fl * 64 + lane]      = b0 * 0.125f;
        catrow[128 + fl * 64 + lane + 32] = b1 * 0.125f;
    }
}

// -------- tf32 helpers --------
__device__ __forceinline__ uint32_t f2tf32(float v) {
    uint32_t r;
    asm("cvt.rna.tf32.f32 %0, %1;" : "=r"(r) : "f"(v));
    return r;
}

__device__ __forceinline__ void mma_tf32(float* c, const uint32_t* a, const uint32_t* b) {
    asm volatile(
        "mma.sync.aligned.m16n8k8.row.col.f32.tf32.tf32.f32 "
        "{%0,%1,%2,%3}, {%4,%5,%6,%7}, {%8,%9}, {%0,%1,%2,%3};"
        : "+f"(c[0]), "+f"(c[1]), "+f"(c[2]), "+f"(c[3])
        : "r"(a[0]), "r"(a[1]), "r"(a[2]), "r"(a[3]), "r"(b[0]), "r"(b[1]));
}

// -------- TF32 tensor-core GEMM: out[M,128] = [A|A2] @ W[K1+K2,128] + bias (+addmat) --------
template <bool RELU>
__global__ __launch_bounds__(256) void gemm_tf32(
    const float* __restrict__ A,  int K1,
    const float* __restrict__ A2, int K2,
    const float* __restrict__ W,
    const float* __restrict__ bias,
    const float* __restrict__ addmat,
    float* __restrict__ out, int M)
{
    __shared__ uint32_t As[128][17];
    __shared__ uint32_t Ws[16][132];

    int tid  = threadIdx.x;
    int lane = tid & 31;
    int wid  = tid >> 5;
    int wm = wid & 1;
    int wn = wid >> 1;
    int g  = lane >> 2;
    int tg = lane & 3;
    int r0 = blockIdx.x * 128;

    float acc[4][4][4];
#pragma unroll
    for (int mt = 0; mt < 4; mt++)
#pragma unroll
        for (int nt = 0; nt < 4; nt++)
#pragma unroll
            for (int u = 0; u < 4; u++) acc[mt][nt][u] = 0.f;

    int K = K1 + K2;
    for (int kt = 0; kt < K; kt += 16) {
        const float* Ab; int stride, kk;
        if (kt < K1) { Ab = A;  stride = K1; kk = kt; }
        else         { Ab = A2; stride = K2; kk = kt - K1; }

#pragma unroll
        for (int l = 0; l < 2; l++) {
            int idx = tid + l * 256;
            int m = idx >> 2, c4 = (idx & 3) * 4;
            int row = r0 + m;
            float4 v = make_float4(0.f, 0.f, 0.f, 0.f);
            if (row < M) v = *(const float4*)(Ab + (size_t)row * stride + kk + c4);
            As[m][c4 + 0] = f2tf32(v.x);
            As[m][c4 + 1] = f2tf32(v.y);
            As[m][c4 + 2] = f2tf32(v.z);
            As[m][c4 + 3] = f2tf32(v.w);
        }
#pragma unroll
        for (int l = 0; l < 2; l++) {
            int idx = tid + l * 256;
            int k = idx >> 5, n4 = (idx & 31) * 4;
            float4 v = *(const float4*)(W + (size_t)(kt + k) * 128 + n4);
            Ws[k][n4 + 0] = f2tf32(v.x);
            Ws[k][n4 + 1] = f2tf32(v.y);
            Ws[k][n4 + 2] = f2tf32(v.z);
            Ws[k][n4 + 3] = f2tf32(v.w);
        }
        __syncthreads();

#pragma unroll
        for (int ks = 0; ks < 16; ks += 8) {
            uint32_t afr[4][4];
#pragma unroll
            for (int mt = 0; mt < 4; mt++) {
                int rb = wm * 64 + mt * 16 + g;
                afr[mt][0] = As[rb    ][ks + tg];
                afr[mt][1] = As[rb + 8][ks + tg];
                afr[mt][2] = As[rb    ][ks + tg + 4];
                afr[mt][3] = As[rb + 8][ks + tg + 4];
            }
            uint32_t bfr[4][2];
#pragma unroll
            for (int nt = 0; nt < 4; nt++) {
                int cb = wn * 32 + nt * 8 + g;
                bfr[nt][0] = Ws[ks + tg    ][cb];
                bfr[nt][1] = Ws[ks + tg + 4][cb];
            }
#pragma unroll
            for (int mt = 0; mt < 4; mt++)
#pragma unroll
                for (int nt = 0; nt < 4; nt++)
                    mma_tf32(acc[mt][nt], afr[mt], bfr[nt]);
        }
        __syncthreads();
    }

#pragma unroll
    for (int mt = 0; mt < 4; mt++) {
#pragma unroll
        for (int nt = 0; nt < 4; nt++) {
            int col = wn * 32 + nt * 8 + tg * 2;
            int rowa = r0 + wm * 64 + mt * 16 + g;
            int rowb = rowa + 8;
            float b0 = bias[col], b1 = bias[col + 1];
            if (rowa < M) {
                float x0 = acc[mt][nt][0] + b0;
                float x1 = acc[mt][nt][1] + b1;
                if (addmat) {
                    x0 += addmat[(size_t)rowa * 128 + col];
                    x1 += addmat[(size_t)rowa * 128 + col + 1];
                }
                if (RELU) { x0 = fmaxf(x0, 0.f); x1 = fmaxf(x1, 0.f); }
                *(float2*)(out + (size_t)rowa * 128 + col) = make_float2(x0, x1);
            }
            if (rowb < M) {
                float x2 = acc[mt][nt][2] + b0;
                float x3 = acc[mt][nt][3] + b1;
                if (addmat) {
                    x2 += addmat[(size_t)rowb * 128 + col];
                    x3 += addmat[(size_t)rowb * 128 + col + 1];
                }
                if (RELU) { x2 = fmaxf(x2, 0.f); x3 = fmaxf(x3, 0.f); }
                *(float2*)(out + (size_t)rowb * 128 + col) = make_float2(x2, x3);
            }
        }
    }
}

// -------- launch --------
extern "C" void kernel_launch(void* const* d_in, const int* in_sizes, int n_in,
                              void* d_out, int out_size) {
    const int*   edge          = (const int*)d_in[0];
    const int*   src           = edge;
    const int*   dstp          = edge + EE;
    const int*   user_features = (const int*)d_in[1];
    const int*   item_features = (const int*)d_in[2];
    const int*   user_text     = (const int*)d_in[3];
    const int*   item_text     = (const int*)d_in[4];
    const float* user_id_emb   = (const float*)d_in[5];
    const float* item_id_emb   = (const float*)d_in[6];
    const float* user_feat_emb = (const float*)d_in[7];
    const float* item_feat_emb = (const float*)d_in[8];
    const float* word_emb      = (const float*)d_in[9];
    const float* user_projW    = (const float*)d_in[10];
    const float* user_projb    = (const float*)d_in[11];
    const float* item_projW    = (const float*)d_in[12];
    const float* item_projb    = (const float*)d_in[13];
    const float* w0W = (const float*)d_in[14];
    const float* w0b = (const float*)d_in[15];
    const float* w1W = (const float*)d_in[16];
    const float* w1b = (const float*)d_in[17];
    const float* v0W = (const float*)d_in[18];
    const float* v0b = (const float*)d_in[19];
    const float* v1W = (const float*)d_in[20];
    const float* v1b = (const float*)d_in[21];

    float *pA, *pB, *pC, *pcat;
    int   *pdeg;
    cudaGetSymbolAddress((void**)&pA,   g_bufA);
    cudaGetSymbolAddress((void**)&pB,   g_bufB);
    cudaGetSymbolAddress((void**)&pC,   g_bufC);
    cudaGetSymbolAddress((void**)&pcat, g_cat);
    cudaGetSymbolAddress((void**)&pdeg, g_deg);

    // ----- CSR build -----
    zero_kernel<<<64, 256>>>((uint4*)pdeg, NNODE / 4);
    deg_kernel<<<(EE + 255) / 256, 256>>>(dstp);
    invdeg_kernel<<<(NNODE + 255) / 256, 256>>>();
    scan1_kernel<<<NBLK, 256>>>();
    scan2_kernel<<<1, 1024>>>();
    scan3_kernel<<<(NNODE + 255) / 256, 256>>>();
    fill_kernel<<<(EE + 255) / 256, 256>>>(src, dstp);

    // ----- node features -> g_cat -----
    embed_kernel<<<(NNODE * 32 + 255) / 256, 256>>>(
        user_features, item_features, user_text, item_text,
        user_feat_emb, item_feat_emb, word_emb);

    // ----- projection (+id_emb) -> x in bufA -----
    gemm_tf32<false><<<(NUSR + 127) / 128, 256>>>(
        pcat, KCAT, nullptr, 0, user_projW, user_projb, user_id_emb, pA, NUSR);
    gemm_tf32<false><<<(NITM + 127) / 128, 256>>>(
        pcat + (size_t)NUSR * KCAT, KCAT, nullptr, 0, item_projW, item_projb, item_id_emb,
        pA + (size_t)NUSR * DD, NITM);

    // ----- layer 0 -----
    agg_kernel<<<(NNODE * 32 + 255) / 256, 256>>>(pA, pB);
    gemm_tf32<true><<<(NNODE + 127) / 128, 256>>>(
        pB, DD, nullptr, 0, v0W, v0b, nullptr, pC, NNODE);
    gemm_tf32<true><<<(NNODE + 127) / 128, 256>>>(
        pA, DD, pC, DD, w0W, w0b, nullptr, pB, NNODE);

    // ----- layer 1 -----
    agg_kernel<<<(NNODE * 32 + 255) / 256, 256>>>(pB, pA);
    gemm_tf32<true><<<(NNODE + 127) / 128, 256>>>(
        pA, DD, nullptr, 0, v1W, v1b, nullptr, pC, NNODE);
    gemm_tf32<false><<<(NNODE + 127) / 128, 256>>>(
        pB, DD, pC, DD, w1W, w1b, nullptr, (float*)d_out, NNODE);
}

// round 4
// speedup vs baseline: 2.9048x; 1.2349x over previous
#include <cuda_runtime.h>
#include <cstdint>

#define NUSR 100000
#define NITM 50000
#define NNODE (NUSR + NITM)
#define DD 128
#define EE 1500000
#define HALFD 64
#define KCAT 320
#define NBLK 586   // ceil(NNODE/256)

// smem pads (conflict-free fragment loads)
#define APAD 20
#define WPAD 136
#define HPAD 132

// -------- scratch (device globals: allocation-free) --------
__device__ float g_bufA[(size_t)NNODE * DD];
__device__ float g_bufB[(size_t)NNODE * DD];
__device__ float g_cat [(size_t)NNODE * KCAT];
__device__ float g_invdeg[NNODE];
__device__ int   g_deg[NNODE];
__device__ int   g_bsum[1024];
__device__ int   g_offs[NNODE + 1];
__device__ int   g_cursor[NNODE];
__device__ int   g_csr[EE];

// -------- utility: zero --------
__global__ void zero_kernel(uint4* __restrict__ p, int n4) {
    int i = blockIdx.x * blockDim.x + threadIdx.x;
    int st = gridDim.x * blockDim.x;
    for (; i < n4; i += st) p[i] = make_uint4(0, 0, 0, 0);
}

// -------- degree count --------
__global__ void deg_kernel(const int* __restrict__ dst) {
    int i = blockIdx.x * blockDim.x + threadIdx.x;
    if (i < EE) atomicAdd(&g_deg[dst[i]], 1);
}

__global__ void invdeg_kernel() {
    int i = blockIdx.x * blockDim.x + threadIdx.x;
    if (i < NNODE) g_invdeg[i] = 1.0f / fmaxf((float)g_deg[i], 1.0f);
}

// -------- scan phase 1 --------
__global__ void scan1_kernel() {
    __shared__ int sm[256];
    int tid = threadIdx.x;
    int i = blockIdx.x * 256 + tid;
    int v = (i < NNODE) ? g_deg[i] : 0;
    sm[tid] = v;
    __syncthreads();
#pragma unroll
    for (int d = 1; d < 256; d <<= 1) {
        int t = (tid >= d) ? sm[tid - d] : 0;
        __syncthreads();
        sm[tid] += t;
        __syncthreads();
    }
    if (i < NNODE) g_offs[i] = sm[tid] - v;
    if (tid == 255) g_bsum[blockIdx.x] = sm[255];
}

// -------- scan phase 2 --------
__global__ void scan2_kernel() {
    __shared__ int sm[1024];
    int tid = threadIdx.x;
    int v = (tid < NBLK) ? g_bsum[tid] : 0;
    sm[tid] = v;
    __syncthreads();
#pragma unroll
    for (int d = 1; d < 1024; d <<= 1) {
        int t = (tid >= d) ? sm[tid - d] : 0;
        __syncthreads();
        sm[tid] += t;
        __syncthreads();
    }
    g_bsum[tid] = sm[tid] - v;
}

// -------- scan phase 3 --------
__global__ void scan3_kernel() {
    int i = blockIdx.x * blockDim.x + threadIdx.x;
    if (i < NNODE) {
        int o = g_offs[i] + g_bsum[i >> 8];
        g_offs[i] = o;
        g_cursor[i] = o;
    }
    if (i == 0) g_offs[NNODE] = EE;
}

// -------- CSR fill --------
__global__ void fill_kernel(const int* __restrict__ src, const int* __restrict__ dst) {
    int i = blockIdx.x * blockDim.x + threadIdx.x;
    if (i < EE) {
        int d = dst[i];
        int pos = atomicAdd(&g_cursor[d], 1);
        g_csr[pos] = src[i];
    }
}

// -------- gather aggregation (warp per node) --------
__global__ void agg_kernel(const float* __restrict__ x, float* __restrict__ out) {
    int gw   = (blockIdx.x * blockDim.x + threadIdx.x) >> 5;
    int lane = threadIdx.x & 31;
    if (gw >= NNODE) return;
    int off = g_offs[gw];
    int end = g_offs[gw + 1];
    float4 acc = make_float4(0.f, 0.f, 0.f, 0.f);
    for (int j = off; j < end; j++) {
        int s = __ldg(&g_csr[j]);
        float4 v = __ldg((const float4*)(x + (size_t)s * DD) + lane);
        acc.x += v.x; acc.y += v.y; acc.z += v.z; acc.w += v.w;
    }
    float sc = g_invdeg[gw];
    acc.x *= sc; acc.y *= sc; acc.z *= sc; acc.w *= sc;
    *((float4*)(out + (size_t)gw * DD) + lane) = acc;
}

// -------- embedding gather --------
__global__ void embed_kernel(const int* __restrict__ uf,  const int* __restrict__ itf,
                             const int* __restrict__ ut,  const int* __restrict__ it,
                             const float* __restrict__ ufe, const float* __restrict__ ife,
                             const float* __restrict__ we) {
    int gw   = (blockIdx.x * blockDim.x + threadIdx.x) >> 5;
    int lane = threadIdx.x & 31;
    if (gw >= NNODE) return;
    int n = gw;
    bool user = n < NUSR;
    const int*   f   = user ? uf + (size_t)n * 10 : itf + (size_t)(n - NUSR) * 10;
    const float* tab = user ? ufe : ife;

    float a0 = 0.f, a1 = 0.f, a2 = 0.f, a3 = 0.f;
#pragma unroll
    for (int j = 0; j < 10; j++) {
        int r = __ldg(f + j);
        const float* tr = tab + (size_t)r * DD + lane;
        a0 += __ldg(tr);      a1 += __ldg(tr + 32);
        a2 += __ldg(tr + 64); a3 += __ldg(tr + 96);
    }
    float* catrow = g_cat + (size_t)n * KCAT;
    catrow[lane]      = a0 * 0.1f;
    catrow[lane + 32] = a1 * 0.1f;
    catrow[lane + 64] = a2 * 0.1f;
    catrow[lane + 96] = a3 * 0.1f;

    const int* t = user ? ut + (size_t)n * 24 : it + (size_t)(n - NUSR) * 24;
#pragma unroll
    for (int fl = 0; fl < 3; fl++) {
        float b0 = 0.f, b1 = 0.f;
#pragma unroll
        for (int w = 0; w < 8; w++) {
            int r = __ldg(t + fl * 8 + w);
            const float* wr = we + (size_t)r * HALFD + lane;
            b0 += __ldg(wr);
            b1 += __ldg(wr + 32);
        }
        catrow[128 + fl * 64 + lane]      = b0 * 0.125f;
        catrow[128 + fl * 64 + lane + 32] = b1 * 0.125f;
    }
}

// -------- tf32 helpers --------
__device__ __forceinline__ uint32_t f2tf32(float v) {
    uint32_t r;
    asm("cvt.rna.tf32.f32 %0, %1;" : "=r"(r) : "f"(v));
    return r;
}

__device__ __forceinline__ void mma_tf32(float* c, const uint32_t* a, const uint32_t* b) {
    asm volatile(
        "mma.sync.aligned.m16n8k8.row.col.f32.tf32.tf32.f32 "
        "{%0,%1,%2,%3}, {%4,%5,%6,%7}, {%8,%9}, {%0,%1,%2,%3};"
        : "+f"(c[0]), "+f"(c[1]), "+f"(c[2]), "+f"(c[3])
        : "r"(a[0]), "r"(a[1]), "r"(a[2]), "r"(a[3]), "r"(b[0]), "r"(b[1]));
}

// -------- TF32 GEMM (projection): out[M,128] = A @ W[K1,128] + bias + addmat --------
__global__ __launch_bounds__(256) void gemm_tf32(
    const float* __restrict__ A,  int K1,
    const float* __restrict__ W,
    const float* __restrict__ bias,
    const float* __restrict__ addmat,
    float* __restrict__ out, int M)
{
    __shared__ uint32_t As[128][APAD];
    __shared__ uint32_t Ws[16][WPAD];

    int tid  = threadIdx.x;
    int lane = tid & 31;
    int wid  = tid >> 5;
    int wm = wid & 1, wn = wid >> 1;
    int g  = lane >> 2, tg = lane & 3;
    int r0 = blockIdx.x * 128;

    float acc[4][4][4];
#pragma unroll
    for (int mt = 0; mt < 4; mt++)
#pragma unroll
        for (int nt = 0; nt < 4; nt++)
#pragma unroll
            for (int u = 0; u < 4; u++) acc[mt][nt][u] = 0.f;

    for (int kt = 0; kt < K1; kt += 16) {
#pragma unroll
        for (int l = 0; l < 2; l++) {
            int idx = tid + l * 256;
            int m = idx >> 2, c4 = (idx & 3) * 4;
            int row = r0 + m;
            float4 v = make_float4(0.f, 0.f, 0.f, 0.f);
            if (row < M) v = *(const float4*)(A + (size_t)row * K1 + kt + c4);
            As[m][c4 + 0] = f2tf32(v.x);
            As[m][c4 + 1] = f2tf32(v.y);
            As[m][c4 + 2] = f2tf32(v.z);
            As[m][c4 + 3] = f2tf32(v.w);
        }
#pragma unroll
        for (int l = 0; l < 2; l++) {
            int idx = tid + l * 256;
            int k = idx >> 5, n4 = (idx & 31) * 4;
            float4 v = *(const float4*)(W + (size_t)(kt + k) * 128 + n4);
            Ws[k][n4 + 0] = f2tf32(v.x);
            Ws[k][n4 + 1] = f2tf32(v.y);
            Ws[k][n4 + 2] = f2tf32(v.z);
            Ws[k][n4 + 3] = f2tf32(v.w);
        }
        __syncthreads();

#pragma unroll
        for (int ks = 0; ks < 16; ks += 8) {
            uint32_t afr[4][4];
#pragma unroll
            for (int mt = 0; mt < 4; mt++) {
                int rb = wm * 64 + mt * 16 + g;
                afr[mt][0] = As[rb    ][ks + tg];
                afr[mt][1] = As[rb + 8][ks + tg];
                afr[mt][2] = As[rb    ][ks + tg + 4];
                afr[mt][3] = As[rb + 8][ks + tg + 4];
            }
            uint32_t bfr[4][2];
#pragma unroll
            for (int nt = 0; nt < 4; nt++) {
                int cb = wn * 32 + nt * 8 + g;
                bfr[nt][0] = Ws[ks + tg    ][cb];
                bfr[nt][1] = Ws[ks + tg + 4][cb];
            }
#pragma unroll
            for (int mt = 0; mt < 4; mt++)
#pragma unroll
                for (int nt = 0; nt < 4; nt++)
                    mma_tf32(acc[mt][nt], afr[mt], bfr[nt]);
        }
        __syncthreads();
    }

#pragma unroll
    for (int mt = 0; mt < 4; mt++) {
#pragma unroll
        for (int nt = 0; nt < 4; nt++) {
            int col = wn * 32 + nt * 8 + tg * 2;
            int rowa = r0 + wm * 64 + mt * 16 + g;
            int rowb = rowa + 8;
            float b0 = bias[col], b1 = bias[col + 1];
            if (rowa < M) {
                float x0 = acc[mt][nt][0] + b0 + addmat[(size_t)rowa * 128 + col];
                float x1 = acc[mt][nt][1] + b1 + addmat[(size_t)rowa * 128 + col + 1];
                *(float2*)(out + (size_t)rowa * 128 + col) = make_float2(x0, x1);
            }
            if (rowb < M) {
                float x2 = acc[mt][nt][2] + b0 + addmat[(size_t)rowb * 128 + col];
                float x3 = acc[mt][nt][3] + b1 + addmat[(size_t)rowb * 128 + col + 1];
                *(float2*)(out + (size_t)rowb * 128 + col) = make_float2(x2, x3);
            }
        }
    }
}

// -------- fused SAGE layer:  h = relu(agg@vW+vb);  out = [x|h]@wW + wb (opt relu) --------
// dynamic smem: As[128][APAD] | Ws[16][WPAD] | Hs[128][HPAD]
template <bool RELU>
__global__ __launch_bounds__(256) void sage_layer(
    const float* __restrict__ agg,   // [N,128] mean-aggregated neighbors
    const float* __restrict__ x,     // [N,128] node state
    const float* __restrict__ vW, const float* __restrict__ vb,
    const float* __restrict__ wW, const float* __restrict__ wb,
    float* __restrict__ out, int M)
{
    extern __shared__ uint32_t dynsm[];
    uint32_t (*As)[APAD] = (uint32_t (*)[APAD])dynsm;
    uint32_t (*Ws)[WPAD] = (uint32_t (*)[WPAD])(dynsm + 128 * APAD);
    uint32_t (*Hs)[HPAD] = (uint32_t (*)[HPAD])(dynsm + 128 * APAD + 16 * WPAD);

    int tid  = threadIdx.x;
    int lane = tid & 31;
    int wid  = tid >> 5;
    int wm = wid & 1, wn = wid >> 1;
    int g  = lane >> 2, tg = lane & 3;
    int r0 = blockIdx.x * 128;

    float acc[4][4][4];
#pragma unroll
    for (int mt = 0; mt < 4; mt++)
#pragma unroll
        for (int nt = 0; nt < 4; nt++)
#pragma unroll
            for (int u = 0; u < 4; u++) acc[mt][nt][u] = 0.f;

    // ---- phase 1: h = relu(agg @ vW + vb) ----
    for (int kt = 0; kt < 128; kt += 16) {
#pragma unroll
        for (int l = 0; l < 2; l++) {
            int idx = tid + l * 256;
            int m = idx >> 2, c4 = (idx & 3) * 4;
            int row = r0 + m;
            float4 v = make_float4(0.f, 0.f, 0.f, 0.f);
            if (row < M) v = *(const float4*)(agg + (size_t)row * DD + kt + c4);
            As[m][c4 + 0] = f2tf32(v.x);
            As[m][c4 + 1] = f2tf32(v.y);
            As[m][c4 + 2] = f2tf32(v.z);
            As[m][c4 + 3] = f2tf32(v.w);
        }
#pragma unroll
        for (int l = 0; l < 2; l++) {
            int idx = tid + l * 256;
            int k = idx >> 5, n4 = (idx & 31) * 4;
            float4 v = *(const float4*)(vW + (size_t)(kt + k) * 128 + n4);
            Ws[k][n4 + 0] = f2tf32(v.x);
            Ws[k][n4 + 1] = f2tf32(v.y);
            Ws[k][n4 + 2] = f2tf32(v.z);
            Ws[k][n4 + 3] = f2tf32(v.w);
        }
        __syncthreads();
#pragma unroll
        for (int ks = 0; ks < 16; ks += 8) {
            uint32_t afr[4][4];
#pragma unroll
            for (int mt = 0; mt < 4; mt++) {
                int rb = wm * 64 + mt * 16 + g;
                afr[mt][0] = As[rb    ][ks + tg];
                afr[mt][1] = As[rb + 8][ks + tg];
                afr[mt][2] = As[rb    ][ks + tg + 4];
                afr[mt][3] = As[rb + 8][ks + tg + 4];
            }
            uint32_t bfr[4][2];
#pragma unroll
            for (int nt = 0; nt < 4; nt++) {
                int cb = wn * 32 + nt * 8 + g;
                bfr[nt][0] = Ws[ks + tg    ][cb];
                bfr[nt][1] = Ws[ks + tg + 4][cb];
            }
#pragma unroll
            for (int mt = 0; mt < 4; mt++)
#pragma unroll
                for (int nt = 0; nt < 4; nt++)
                    mma_tf32(acc[mt][nt], afr[mt], bfr[nt]);
        }
        __syncthreads();
    }

    // write h -> Hs (tf32, relu + bias), reset acc
#pragma unroll
    for (int mt = 0; mt < 4; mt++) {
#pragma unroll
        for (int nt = 0; nt < 4; nt++) {
            int col = wn * 32 + nt * 8 + tg * 2;
            int ra = wm * 64 + mt * 16 + g;
            float b0 = vb[col], b1 = vb[col + 1];
            Hs[ra    ][col    ] = f2tf32(fmaxf(acc[mt][nt][0] + b0, 0.f));
            Hs[ra    ][col + 1] = f2tf32(fmaxf(acc[mt][nt][1] + b1, 0.f));
            Hs[ra + 8][col    ] = f2tf32(fmaxf(acc[mt][nt][2] + b0, 0.f));
            Hs[ra + 8][col + 1] = f2tf32(fmaxf(acc[mt][nt][3] + b1, 0.f));
#pragma unroll
            for (int u = 0; u < 4; u++) acc[mt][nt][u] = 0.f;
        }
    }
    __syncthreads();

    // ---- phase 2: out = x @ wW[0:128] + h @ wW[128:256] + wb ----
    for (int kt = 0; kt < 256; kt += 16) {
        if (kt < 128) {
#pragma unroll
            for (int l = 0; l < 2; l++) {
                int idx = tid + l * 256;
                int m = idx >> 2, c4 = (idx & 3) * 4;
                int row = r0 + m;
                float4 v = make_float4(0.f, 0.f, 0.f, 0.f);
                if (row < M) v = *(const float4*)(x + (size_t)row * DD + kt + c4);
                As[m][c4 + 0] = f2tf32(v.x);
                As[m][c4 + 1] = f2tf32(v.y);
                As[m][c4 + 2] = f2tf32(v.z);
                As[m][c4 + 3] = f2tf32(v.w);
            }
        }
#pragma unroll
        for (int l = 0; l < 2; l++) {
            int idx = tid + l * 256;
            int k = idx >> 5, n4 = (idx & 31) * 4;
            float4 v = *(const float4*)(wW + (size_t)(kt + k) * 128 + n4);
            Ws[k][n4 + 0] = f2tf32(v.x);
            Ws[k][n4 + 1] = f2tf32(v.y);
            Ws[k][n4 + 2] = f2tf32(v.z);
            Ws[k][n4 + 3] = f2tf32(v.w);
        }
        __syncthreads();
        int hc = kt - 128;
#pragma unroll
        for (int ks = 0; ks < 16; ks += 8) {
            uint32_t afr[4][4];
#pragma unroll
            for (int mt = 0; mt < 4; mt++) {
                int rb = wm * 64 + mt * 16 + g;
                if (kt < 128) {
                    afr[mt][0] = As[rb    ][ks + tg];
                    afr[mt][1] = As[rb + 8][ks + tg];
                    afr[mt][2] = As[rb    ][ks + tg + 4];
                    afr[mt][3] = As[rb + 8][ks + tg + 4];
                } else {
                    afr[mt][0] = Hs[rb    ][hc + ks + tg];
                    afr[mt][1] = Hs[rb + 8][hc + ks + tg];
                    afr[mt][2] = Hs[rb    ][hc + ks + tg + 4];
                    afr[mt][3] = Hs[rb + 8][hc + ks + tg + 4];
                }
            }
            uint32_t bfr[4][2];
#pragma unroll
            for (int nt = 0; nt < 4; nt++) {
                int cb = wn * 32 + nt * 8 + g;
                bfr[nt][0] = Ws[ks + tg    ][cb];
                bfr[nt][1] = Ws[ks + tg + 4][cb];
            }
#pragma unroll
            for (int mt = 0; mt < 4; mt++)
#pragma unroll
                for (int nt = 0; nt < 4; nt++)
                    mma_tf32(acc[mt][nt], afr[mt], bfr[nt]);
        }
        __syncthreads();
    }

    // epilogue
#pragma unroll
    for (int mt = 0; mt < 4; mt++) {
#pragma unroll
        for (int nt = 0; nt < 4; nt++) {
            int col = wn * 32 + nt * 8 + tg * 2;
            int rowa = r0 + wm * 64 + mt * 16 + g;
            int rowb = rowa + 8;
            float b0 = wb[col], b1 = wb[col + 1];
            if (rowa < M) {
                float x0 = acc[mt][nt][0] + b0;
                float x1 = acc[mt][nt][1] + b1;
                if (RELU) { x0 = fmaxf(x0, 0.f); x1 = fmaxf(x1, 0.f); }
                *(float2*)(out + (size_t)rowa * 128 + col) = make_float2(x0, x1);
            }
            if (rowb < M) {
                float x2 = acc[mt][nt][2] + b0;
                float x3 = acc[mt][nt][3] + b1;
                if (RELU) { x2 = fmaxf(x2, 0.f); x3 = fmaxf(x3, 0.f); }
                *(float2*)(out + (size_t)rowb * 128 + col) = make_float2(x2, x3);
            }
        }
    }
}

// -------- launch --------
extern "C" void kernel_launch(void* const* d_in, const int* in_sizes, int n_in,
                              void* d_out, int out_size) {
    const int*   edge          = (const int*)d_in[0];
    const int*   src           = edge;
    const int*   dstp          = edge + EE;
    const int*   user_features = (const int*)d_in[1];
    const int*   item_features = (const int*)d_in[2];
    const int*   user_text     = (const int*)d_in[3];
    const int*   item_text     = (const int*)d_in[4];
    const float* user_id_emb   = (const float*)d_in[5];
    const float* item_id_emb   = (const float*)d_in[6];
    const float* user_feat_emb = (const float*)d_in[7];
    const float* item_feat_emb = (const float*)d_in[8];
    const float* word_emb      = (const float*)d_in[9];
    const float* user_projW    = (const float*)d_in[10];
    const float* user_projb    = (const float*)d_in[11];
    const float* item_projW    = (const float*)d_in[12];
    const float* item_projb    = (const float*)d_in[13];
    const float* w0W = (const float*)d_in[14];
    const float* w0b = (const float*)d_in[15];
    const float* w1W = (const float*)d_in[16];
    const float* w1b = (const float*)d_in[17];
    const float* v0W = (const float*)d_in[18];
    const float* v0b = (const float*)d_in[19];
    const float* v1W = (const float*)d_in[20];
    const float* v1b = (const float*)d_in[21];

    float *pA, *pB, *pcat;
    int   *pdeg;
    cudaGetSymbolAddress((void**)&pA,   g_bufA);
    cudaGetSymbolAddress((void**)&pB,   g_bufB);
    cudaGetSymbolAddress((void**)&pcat, g_cat);
    cudaGetSymbolAddress((void**)&pdeg, g_deg);

    const int SAGE_SMEM = (128 * APAD + 16 * WPAD + 128 * HPAD) * 4;
    cudaFuncSetAttribute(sage_layer<true>,  cudaFuncAttributeMaxDynamicSharedMemorySize, SAGE_SMEM);
    cudaFuncSetAttribute(sage_layer<false>, cudaFuncAttributeMaxDynamicSharedMemorySize, SAGE_SMEM);

    // order chosen so launch index 3 = user projection GEMM (profiler slot)
    zero_kernel<<<64, 256>>>((uint4*)pdeg, NNODE / 4);                       // 0
    embed_kernel<<<(NNODE * 32 + 255) / 256, 256>>>(                         // 1
        user_features, item_features, user_text, item_text,
        user_feat_emb, item_feat_emb, word_emb);
    deg_kernel<<<(EE + 255) / 256, 256>>>(dstp);                             // 2
    gemm_tf32<<<(NUSR + 127) / 128, 256>>>(                                  // 3 (profiled)
        pcat, KCAT, user_projW, user_projb, user_id_emb, pA, NUSR);
    gemm_tf32<<<(NITM + 127) / 128, 256>>>(                                  // 4
        pcat + (size_t)NUSR * KCAT, KCAT, item_projW, item_projb, item_id_emb,
        pA + (size_t)NUSR * DD, NITM);
    invdeg_kernel<<<(NNODE + 255) / 256, 256>>>();                           // 5
    scan1_kernel<<<NBLK, 256>>>();                                           // 6
    scan2_kernel<<<1, 1024>>>();                                             // 7
    scan3_kernel<<<(NNODE + 255) / 256, 256>>>();                            // 8
    fill_kernel<<<(EE + 255) / 256, 256>>>(src, dstp);                       // 9

    // ----- layer 0:  agg -> bufB;  x=bufA -> out bufB (fused, reuse agg buf as out? no: need agg during) -----
    agg_kernel<<<(NNODE * 32 + 255) / 256, 256>>>(pA, pB);                   // 10
    // fused layer reads agg=pB and x=pA, writes new x -> g_cat (reuse as scratch, 76.8MB < 192MB)
    sage_layer<true><<<(NNODE + 127) / 128, 256, SAGE_SMEM>>>(               // 11
        pB, pA, v0W, v0b, w0W, w0b, pcat, NNODE);

    // ----- layer 1 -----
    agg_kernel<<<(NNODE * 32 + 255) / 256, 256>>>(pcat, pA);                 // 12
    sage_layer<false><<<(NNODE + 127) / 128, 256, SAGE_SMEM>>>(              // 13
        pA, pcat, v1W, v1b, w1W, w1b, (float*)d_out, NNODE);
}

// round 5
// speedup vs baseline: 3.2716x; 1.1263x over previous
#include <cuda_runtime.h>
#include <cstdint>

#define NUSR 100000
#define NITM 50000
#define NNODE (NUSR + NITM)
#define DD 128
#define EE 1500000
#define HALFD 64
#define KCAT 320
#define NBLK 586   // ceil(NNODE/256)

#define APAD16 20
#define APAD32 36
#define WPAD 136
#define HPAD 132

// weight buffer offsets (floats)
#define OFF_U  0
#define OFF_I  40960
#define OFF_W0 81920
#define OFF_W1 114688
#define OFF_V0 147456
#define OFF_V1 163840
#define WTOT   180224

// -------- scratch (device globals: allocation-free) --------
__device__ float g_bufA[(size_t)NNODE * DD];
__device__ float g_bufB[(size_t)NNODE * DD];
__device__ float g_cat [(size_t)NNODE * KCAT];
__device__ float g_wts [WTOT];
__device__ float g_invdeg[NNODE];
__device__ int   g_deg[NNODE];
__device__ int   g_bsum[1024];
__device__ int   g_offs[NNODE + 1];
__device__ int   g_cursor[NNODE];
__device__ int   g_csr[EE];

// -------- tf32 helpers --------
__device__ __forceinline__ uint32_t f2tf32(float v) {
    uint32_t r;
    asm("cvt.rna.tf32.f32 %0, %1;" : "=r"(r) : "f"(v));
    return r;
}
__device__ __forceinline__ float rtf(float v) { return __uint_as_float(f2tf32(v)); }

__device__ __forceinline__ void mma_tf32(float* c, const uint32_t* a, const uint32_t* b) {
    asm volatile(
        "mma.sync.aligned.m16n8k8.row.col.f32.tf32.tf32.f32 "
        "{%0,%1,%2,%3}, {%4,%5,%6,%7}, {%8,%9}, {%0,%1,%2,%3};"
        : "+f"(c[0]), "+f"(c[1]), "+f"(c[2]), "+f"(c[3])
        : "r"(a[0]), "r"(a[1]), "r"(a[2]), "r"(a[3]), "r"(b[0]), "r"(b[1]));
}

__device__ __forceinline__ void cp16(void* smem_dst, const void* gsrc, bool pred) {
    uint32_t dst = (uint32_t)__cvta_generic_to_shared(smem_dst);
    int sz = pred ? 16 : 0;
    asm volatile("cp.async.ca.shared.global [%0], [%1], 16, %2;\n"
                 :: "r"(dst), "l"(gsrc), "r"(sz));
}
__device__ __forceinline__ void cp_commit() { asm volatile("cp.async.commit_group;\n"); }
__device__ __forceinline__ void cp_wait1()  { asm volatile("cp.async.wait_group 1;\n"); }
__device__ __forceinline__ void cp_wait0()  { asm volatile("cp.async.wait_group 0;\n"); }

// -------- utility kernels --------
__global__ void zero_kernel(uint4* __restrict__ p, int n4) {
    int i = blockIdx.x * blockDim.x + threadIdx.x;
    int st = gridDim.x * blockDim.x;
    for (; i < n4; i += st) p[i] = make_uint4(0, 0, 0, 0);
}

__global__ void roundw_kernel(const float* __restrict__ uW, const float* __restrict__ iW,
                              const float* __restrict__ w0, const float* __restrict__ w1,
                              const float* __restrict__ v0, const float* __restrict__ v1) {
    int i = blockIdx.x * blockDim.x + threadIdx.x;
    if (i >= WTOT) return;
    float v;
    if      (i < OFF_I)  v = uW[i - OFF_U];
    else if (i < OFF_W0) v = iW[i - OFF_I];
    else if (i < OFF_W1) v = w0[i - OFF_W0];
    else if (i < OFF_V0) v = w1[i - OFF_W1];
    else if (i < OFF_V1) v = v0[i - OFF_V0];
    else                 v = v1[i - OFF_V1];
    g_wts[i] = rtf(v);
}

__global__ void deg_kernel(const int* __restrict__ dst) {
    int i = blockIdx.x * blockDim.x + threadIdx.x;
    if (i < EE) atomicAdd(&g_deg[dst[i]], 1);
}

__global__ void invdeg_kernel() {
    int i = blockIdx.x * blockDim.x + threadIdx.x;
    if (i < NNODE) g_invdeg[i] = 1.0f / fmaxf((float)g_deg[i], 1.0f);
}

__global__ void scan1_kernel() {
    __shared__ int sm[256];
    int tid = threadIdx.x;
    int i = blockIdx.x * 256 + tid;
    int v = (i < NNODE) ? g_deg[i] : 0;
    sm[tid] = v;
    __syncthreads();
#pragma unroll
    for (int d = 1; d < 256; d <<= 1) {
        int t = (tid >= d) ? sm[tid - d] : 0;
        __syncthreads();
        sm[tid] += t;
        __syncthreads();
    }
    if (i < NNODE) g_offs[i] = sm[tid] - v;
    if (tid == 255) g_bsum[blockIdx.x] = sm[255];
}

__global__ void scan2_kernel() {
    __shared__ int sm[1024];
    int tid = threadIdx.x;
    int v = (tid < NBLK) ? g_bsum[tid] : 0;
    sm[tid] = v;
    __syncthreads();
#pragma unroll
    for (int d = 1; d < 1024; d <<= 1) {
        int t = (tid >= d) ? sm[tid - d] : 0;
        __syncthreads();
        sm[tid] += t;
        __syncthreads();
    }
    g_bsum[tid] = sm[tid] - v;
}

__global__ void scan3_kernel() {
    int i = blockIdx.x * blockDim.x + threadIdx.x;
    if (i < NNODE) {
        int o = g_offs[i] + g_bsum[i >> 8];
        g_offs[i] = o;
        g_cursor[i] = o;
    }
    if (i == 0) g_offs[NNODE] = EE;
}

__global__ void fill_kernel(const int* __restrict__ src, const int* __restrict__ dst) {
    int i = blockIdx.x * blockDim.x + threadIdx.x;
    if (i < EE) {
        int d = dst[i];
        int pos = atomicAdd(&g_cursor[d], 1);
        g_csr[pos] = src[i];
    }
}

// -------- gather aggregation (warp per node), tf32-rounded output --------
__global__ void agg_kernel(const float* __restrict__ x, float* __restrict__ out) {
    int gw   = (blockIdx.x * blockDim.x + threadIdx.x) >> 5;
    int lane = threadIdx.x & 31;
    if (gw >= NNODE) return;
    int off = g_offs[gw];
    int end = g_offs[gw + 1];
    float4 acc = make_float4(0.f, 0.f, 0.f, 0.f);
    for (int j = off; j < end; j++) {
        int s = __ldg(&g_csr[j]);
        float4 v = __ldg((const float4*)(x + (size_t)s * DD) + lane);
        acc.x += v.x; acc.y += v.y; acc.z += v.z; acc.w += v.w;
    }
    float sc = g_invdeg[gw];
    acc.x = rtf(acc.x * sc); acc.y = rtf(acc.y * sc);
    acc.z = rtf(acc.z * sc); acc.w = rtf(acc.w * sc);
    *((float4*)(out + (size_t)gw * DD) + lane) = acc;
}

// -------- embedding gather (tf32-rounded output) --------
__global__ void embed_kernel(const int* __restrict__ uf,  const int* __restrict__ itf,
                             const int* __restrict__ ut,  const int* __restrict__ it,
                             const float* __restrict__ ufe, const float* __restrict__ ife,
                             const float* __restrict__ we) {
    int gw   = (blockIdx.x * blockDim.x + threadIdx.x) >> 5;
    int lane = threadIdx.x & 31;
    if (gw >= NNODE) return;
    int n = gw;
    bool user = n < NUSR;
    const int*   f   = user ? uf + (size_t)n * 10 : itf + (size_t)(n - NUSR) * 10;
    const float* tab = user ? ufe : ife;

    float a0 = 0.f, a1 = 0.f, a2 = 0.f, a3 = 0.f;
#pragma unroll
    for (int j = 0; j < 10; j++) {
        int r = __ldg(f + j);
        const float* tr = tab + (size_t)r * DD + lane;
        a0 += __ldg(tr);      a1 += __ldg(tr + 32);
        a2 += __ldg(tr + 64); a3 += __ldg(tr + 96);
    }
    float* catrow = g_cat + (size_t)n * KCAT;
    catrow[lane]      = rtf(a0 * 0.1f);
    catrow[lane + 32] = rtf(a1 * 0.1f);
    catrow[lane + 64] = rtf(a2 * 0.1f);
    catrow[lane + 96] = rtf(a3 * 0.1f);

    const int* t = user ? ut + (size_t)n * 24 : it + (size_t)(n - NUSR) * 24;
#pragma unroll
    for (int fl = 0; fl < 3; fl++) {
        float b0 = 0.f, b1 = 0.f;
#pragma unroll
        for (int w = 0; w < 8; w++) {
            int r = __ldg(t + fl * 8 + w);
            const float* wr = we + (size_t)r * HALFD + lane;
            b0 += __ldg(wr);
            b1 += __ldg(wr + 32);
        }
        catrow[128 + fl * 64 + lane]      = rtf(b0 * 0.125f);
        catrow[128 + fl * 64 + lane + 32] = rtf(b1 * 0.125f);
    }
}

// ======== pipelined TF32 GEMM (projection), BK=32, cp.async double-buffer ========
// out[M,128] = A[M,K1] @ Wt[K1,128] + bias + addmat  (output tf32-rounded)
// dyn smem: As[2][128][APAD32] | Ws[2][32][WPAD]
__global__ __launch_bounds__(256) void gemm_tf32(
    const float* __restrict__ A,  int K1, int woff,
    const float* __restrict__ bias,
    const float* __restrict__ addmat,
    float* __restrict__ out, int M)
{
    extern __shared__ float sm_[];
    float (*As)[128][APAD32] = (float (*)[128][APAD32])sm_;
    float (*Ws)[32][WPAD]    = (float (*)[32][WPAD])(sm_ + 2 * 128 * APAD32);
    const float* Wt = g_wts + woff;

    int tid  = threadIdx.x;
    int lane = tid & 31;
    int wid  = tid >> 5;
    int wm = wid & 1, wn = wid >> 1;
    int g  = lane >> 2, tg = lane & 3;
    int r0 = blockIdx.x * 128;

    float acc[4][4][4];
#pragma unroll
    for (int mt = 0; mt < 4; mt++)
#pragma unroll
        for (int nt = 0; nt < 4; nt++)
#pragma unroll
            for (int u = 0; u < 4; u++) acc[mt][nt][u] = 0.f;

    int T = K1 / 32;
    auto issue = [&](int t, int s) {
#pragma unroll
        for (int l = 0; l < 4; l++) {
            int idx = tid + l * 256;
            int m = idx >> 3, c8 = (idx & 7) * 4;
            int row = r0 + m;
            cp16(&As[s][m][c8], A + (size_t)row * K1 + t * 32 + c8, row < M);
        }
#pragma unroll
        for (int l = 0; l < 4; l++) {
            int idx = tid + l * 256;
            int k = idx >> 5, n4 = (idx & 31) * 4;
            cp16(&Ws[s][k][n4], Wt + (size_t)(t * 32 + k) * 128 + n4, true);
        }
        cp_commit();
    };

    issue(0, 0);
    for (int t = 0; t < T; t++) {
        int s = t & 1;
        if (t + 1 < T) { issue(t + 1, s ^ 1); cp_wait1(); }
        else cp_wait0();
        __syncthreads();
#pragma unroll
        for (int ks = 0; ks < 32; ks += 8) {
            uint32_t afr[4][4];
#pragma unroll
            for (int mt = 0; mt < 4; mt++) {
                int rb = wm * 64 + mt * 16 + g;
                afr[mt][0] = __float_as_uint(As[s][rb    ][ks + tg]);
                afr[mt][1] = __float_as_uint(As[s][rb + 8][ks + tg]);
                afr[mt][2] = __float_as_uint(As[s][rb    ][ks + tg + 4]);
                afr[mt][3] = __float_as_uint(As[s][rb + 8][ks + tg + 4]);
            }
            uint32_t bfr[4][2];
#pragma unroll
            for (int nt = 0; nt < 4; nt++) {
                int cb = wn * 32 + nt * 8 + g;
                bfr[nt][0] = __float_as_uint(Ws[s][ks + tg    ][cb]);
                bfr[nt][1] = __float_as_uint(Ws[s][ks + tg + 4][cb]);
            }
#pragma unroll
            for (int mt = 0; mt < 4; mt++)
#pragma unroll
                for (int nt = 0; nt < 4; nt++)
                    mma_tf32(acc[mt][nt], afr[mt], bfr[nt]);
        }
        __syncthreads();
    }

#pragma unroll
    for (int mt = 0; mt < 4; mt++) {
#pragma unroll
        for (int nt = 0; nt < 4; nt++) {
            int col = wn * 32 + nt * 8 + tg * 2;
            int rowa = r0 + wm * 64 + mt * 16 + g;
            int rowb = rowa + 8;
            float b0 = bias[col], b1 = bias[col + 1];
            if (rowa < M) {
                float x0 = rtf(acc[mt][nt][0] + b0 + addmat[(size_t)rowa * 128 + col]);
                float x1 = rtf(acc[mt][nt][1] + b1 + addmat[(size_t)rowa * 128 + col + 1]);
                *(float2*)(out + (size_t)rowa * 128 + col) = make_float2(x0, x1);
            }
            if (rowb < M) {
                float x2 = rtf(acc[mt][nt][2] + b0 + addmat[(size_t)rowb * 128 + col]);
                float x3 = rtf(acc[mt][nt][3] + b1 + addmat[(size_t)rowb * 128 + col + 1]);
                *(float2*)(out + (size_t)rowb * 128 + col) = make_float2(x2, x3);
            }
        }
    }
}

// ======== fused SAGE layer, BK=16, cp.async double-buffer ========
// h = relu(agg@vW+vb) in smem; out = x@wW_top + h@wW_bot + wb (opt relu, opt round)
// dyn smem: As[2][128][APAD16] | Ws[2][16][WPAD] | Hs[128][HPAD]
template <bool RELU>
__global__ __launch_bounds__(256) void sage_layer(
    const float* __restrict__ agg, const float* __restrict__ x,
    int voff, const float* __restrict__ vb,
    int woff, const float* __restrict__ wb,
    float* __restrict__ out, int M)
{
    extern __shared__ float sm_[];
    float (*As)[128][APAD16] = (float (*)[128][APAD16])sm_;
    float (*Ws)[16][WPAD]    = (float (*)[16][WPAD])(sm_ + 2 * 128 * APAD16);
    float (*Hs)[HPAD]        = (float (*)[HPAD])(sm_ + 2 * 128 * APAD16 + 2 * 16 * WPAD);
    const float* vW = g_wts + voff;
    const float* wW = g_wts + woff;

    int tid  = threadIdx.x;
    int lane = tid & 31;
    int wid  = tid >> 5;
    int wm = wid & 1, wn = wid >> 1;
    int g  = lane >> 2, tg = lane & 3;
    int r0 = blockIdx.x * 128;

    float acc[4][4][4];
#pragma unroll
    for (int mt = 0; mt < 4; mt++)
#pragma unroll
        for (int nt = 0; nt < 4; nt++)
#pragma unroll
            for (int u = 0; u < 4; u++) acc[mt][nt][u] = 0.f;

    auto issueA = [&](const float* Ap, int t, int s) {
#pragma unroll
        for (int l = 0; l < 2; l++) {
            int idx = tid + l * 256;
            int m = idx >> 2, c4 = (idx & 3) * 4;
            int row = r0 + m;
            cp16(&As[s][m][c4], Ap + (size_t)row * DD + t * 16 + c4, row < M);
        }
    };
    auto issueW = [&](const float* Wp, int t, int s) {
#pragma unroll
        for (int l = 0; l < 2; l++) {
            int idx = tid + l * 256;
            int k = idx >> 5, n4 = (idx & 31) * 4;
            cp16(&Ws[s][k][n4], Wp + (size_t)(t * 16 + k) * 128 + n4, true);
        }
    };

    auto compute = [&](int s, const float* hsrc, int hc) {
#pragma unroll
        for (int ks = 0; ks < 16; ks += 8) {
            uint32_t afr[4][4];
#pragma unroll
            for (int mt = 0; mt < 4; mt++) {
                int rb = wm * 64 + mt * 16 + g;
                if (hsrc == nullptr) {
                    afr[mt][0] = __float_as_uint(As[s][rb    ][ks + tg]);
                    afr[mt][1] = __float_as_uint(As[s][rb + 8][ks + tg]);
                    afr[mt][2] = __float_as_uint(As[s][rb    ][ks + tg + 4]);
                    afr[mt][3] = __float_as_uint(As[s][rb + 8][ks + tg + 4]);
                } else {
                    afr[mt][0] = __float_as_uint(Hs[rb    ][hc + ks + tg]);
                    afr[mt][1] = __float_as_uint(Hs[rb + 8][hc + ks + tg]);
                    afr[mt][2] = __float_as_uint(Hs[rb    ][hc + ks + tg + 4]);
                    afr[mt][3] = __float_as_uint(Hs[rb + 8][hc + ks + tg + 4]);
                }
            }
            uint32_t bfr[4][2];
#pragma unroll
            for (int nt = 0; nt < 4; nt++) {
                int cb = wn * 32 + nt * 8 + g;
                bfr[nt][0] = __float_as_uint(Ws[s][ks + tg    ][cb]);
                bfr[nt][1] = __float_as_uint(Ws[s][ks + tg + 4][cb]);
            }
#pragma unroll
            for (int mt = 0; mt < 4; mt++)
#pragma unroll
                for (int nt = 0; nt < 4; nt++)
                    mma_tf32(acc[mt][nt], afr[mt], bfr[nt]);
        }
    };

    // ---- phase 1: h = relu(agg @ vW + vb), 8 tiles ----
    issueA(agg, 0, 0); issueW(vW, 0, 0); cp_commit();
    for (int t = 0; t < 8; t++) {
        int s = t & 1;
        if (t < 7) { issueA(agg, t + 1, s ^ 1); issueW(vW, t + 1, s ^ 1); cp_commit(); cp_wait1(); }
        else cp_wait0();
        __syncthreads();
        compute(s, nullptr, 0);
        __syncthreads();
    }

    // write h -> Hs (tf32-rounded), reset acc; prefetch phase-2 tile 0 first
    issueA(x, 0, 0); issueW(wW, 0, 0); cp_commit();
#pragma unroll
    for (int mt = 0; mt < 4; mt++) {
#pragma unroll
        for (int nt = 0; nt < 4; nt++) {
            int col = wn * 32 + nt * 8 + tg * 2;
            int ra = wm * 64 + mt * 16 + g;
            float b0 = vb[col], b1 = vb[col + 1];
            Hs[ra    ][col    ] = rtf(fmaxf(acc[mt][nt][0] + b0, 0.f));
            Hs[ra    ][col + 1] = rtf(fmaxf(acc[mt][nt][1] + b1, 0.f));
            Hs[ra + 8][col    ] = rtf(fmaxf(acc[mt][nt][2] + b0, 0.f));
            Hs[ra + 8][col + 1] = rtf(fmaxf(acc[mt][nt][3] + b1, 0.f));
#pragma unroll
            for (int u = 0; u < 4; u++) acc[mt][nt][u] = 0.f;
        }
    }
    __syncthreads();

    // ---- phase 2: out = x @ wW[0:128] + h @ wW[128:256] + wb, 16 tiles ----
    for (int t = 0; t < 16; t++) {
        int s = t & 1;
        if (t < 15) {
            if (t + 1 < 8) issueA(x, t + 1, s ^ 1);
            issueW(wW, t + 1, s ^ 1);
            cp_commit(); cp_wait1();
        } else cp_wait0();
        __syncthreads();
        if (t < 8) compute(s, nullptr, 0);
        else       compute(s, (const float*)1, (t - 8) * 16);
        __syncthreads();
    }

    // epilogue
#pragma unroll
    for (int mt = 0; mt < 4; mt++) {
#pragma unroll
        for (int nt = 0; nt < 4; nt++) {
            int col = wn * 32 + nt * 8 + tg * 2;
            int rowa = r0 + wm * 64 + mt * 16 + g;
            int rowb = rowa + 8;
            float b0 = wb[col], b1 = wb[col + 1];
            if (rowa < M) {
                float x0 = acc[mt][nt][0] + b0;
                float x1 = acc[mt][nt][1] + b1;
                if (RELU) { x0 = rtf(fmaxf(x0, 0.f)); x1 = rtf(fmaxf(x1, 0.f)); }
                *(float2*)(out + (size_t)rowa * 128 + col) = make_float2(x0, x1);
            }
            if (rowb < M) {
                float x2 = acc[mt][nt][2] + b0;
                float x3 = acc[mt][nt][3] + b1;
                if (RELU) { x2 = rtf(fmaxf(x2, 0.f)); x3 = rtf(fmaxf(x3, 0.f)); }
                *(float2*)(out + (size_t)rowb * 128 + col) = make_float2(x2, x3);
            }
        }
    }
}

// -------- launch --------
extern "C" void kernel_launch(void* const* d_in, const int* in_sizes, int n_in,
                              void* d_out, int out_size) {
    const int*   edge          = (const int*)d_in[0];
    const int*   src           = edge;
    const int*   dstp          = edge + EE;
    const int*   user_features = (const int*)d_in[1];
    const int*   item_features = (const int*)d_in[2];
    const int*   user_text     = (const int*)d_in[3];
    const int*   item_text     = (const int*)d_in[4];
    const float* user_id_emb   = (const float*)d_in[5];
    const float* item_id_emb   = (const float*)d_in[6];
    const float* user_feat_emb = (const float*)d_in[7];
    const float* item_feat_emb = (const float*)d_in[8];
    const float* word_emb      = (const float*)d_in[9];
    const float* user_projW    = (const float*)d_in[10];
    const float* user_projb    = (const float*)d_in[11];
    const float* item_projW    = (const float*)d_in[12];
    const float* item_projb    = (const float*)d_in[13];
    const float* w0W = (const float*)d_in[14];
    const float* w0b = (const float*)d_in[15];
    const float* w1W = (const float*)d_in[16];
    const float* w1b = (const float*)d_in[17];
    const float* v0W = (const float*)d_in[18];
    const float* v0b = (const float*)d_in[19];
    const float* v1W = (const float*)d_in[20];
    const float* v1b = (const float*)d_in[21];

    float *pA, *pB, *pcat;
    int   *pdeg;
    cudaGetSymbolAddress((void**)&pA,   g_bufA);
    cudaGetSymbolAddress((void**)&pB,   g_bufB);
    cudaGetSymbolAddress((void**)&pcat, g_cat);
    cudaGetSymbolAddress((void**)&pdeg, g_deg);

    const int GEMM_SMEM = (2 * 128 * APAD32 + 2 * 32 * WPAD) * 4;
    const int SAGE_SMEM = (2 * 128 * APAD16 + 2 * 16 * WPAD + 128 * HPAD) * 4;
    cudaFuncSetAttribute(gemm_tf32, cudaFuncAttributeMaxDynamicSharedMemorySize, GEMM_SMEM);
    cudaFuncSetAttribute(sage_layer<true>,  cudaFuncAttributeMaxDynamicSharedMemorySize, SAGE_SMEM);
    cudaFuncSetAttribute(sage_layer<false>, cudaFuncAttributeMaxDynamicSharedMemorySize, SAGE_SMEM);

    // order: launch index 3 = user projection GEMM (profiler slot)
    zero_kernel<<<64, 256>>>((uint4*)pdeg, NNODE / 4);                       // 0
    embed_kernel<<<(NNODE * 32 + 255) / 256, 256>>>(                         // 1
        user_features, item_features, user_text, item_text,
        user_feat_emb, item_feat_emb, word_emb);
    roundw_kernel<<<(WTOT + 255) / 256, 256>>>(user_projW, item_projW,       // 2
                                               w0W, w1W, v0W, v1W);
    gemm_tf32<<<(NUSR + 127) / 128, 256, GEMM_SMEM>>>(                       // 3 (profiled)
        pcat, KCAT, OFF_U, user_projb, user_id_emb, pA, NUSR);
    gemm_tf32<<<(NITM + 127) / 128, 256, GEMM_SMEM>>>(                       // 4
        pcat + (size_t)NUSR * KCAT, KCAT, OFF_I, item_projb, item_id_emb,
        pA + (size_t)NUSR * DD, NITM);
    deg_kernel<<<(EE + 255) / 256, 256>>>(dstp);                             // 5
    invdeg_kernel<<<(NNODE + 255) / 256, 256>>>();                           // 6
    scan1_kernel<<<NBLK, 256>>>();                                           // 7
    scan2_kernel<<<1, 1024>>>();                                             // 8
    scan3_kernel<<<(NNODE + 255) / 256, 256>>>();                            // 9
    fill_kernel<<<(EE + 255) / 256, 256>>>(src, dstp);                       // 10

    // ----- layer 0 -----
    agg_kernel<<<(NNODE * 32 + 255) / 256, 256>>>(pA, pB);                   // 11
    sage_layer<true><<<(NNODE + 127) / 128, 256, SAGE_SMEM>>>(               // 12
        pB, pA, OFF_V0, v0b, OFF_W0, w0b, pcat, NNODE);

    // ----- layer 1 -----
    agg_kernel<<<(NNODE * 32 + 255) / 256, 256>>>(pcat, pA);                 // 13
    sage_layer<false><<<(NNODE + 127) / 128, 256, SAGE_SMEM>>>(              // 14
        pA, pcat, OFF_V1, v1b, OFF_W1, w1b, (float*)d_out, NNODE);
}

// round 6
// speedup vs baseline: 3.3352x; 1.0194x over previous
#include <cuda_runtime.h>
#include <cstdint>

#define NUSR 100000
#define NITM 50000
#define NNODE (NUSR + NITM)
#define DD 128
#define EE 1500000
#define HALFD 64
#define KCAT 320
#define NBLK 586   // ceil(NNODE/256)

#define APAD16 20
#define APAD32 36
#define WPAD 136

// weight buffer offsets (floats)
#define OFF_U  0
#define OFF_I  40960
#define OFF_W0 81920
#define OFF_W1 114688
#define OFF_V0 147456
#define OFF_V1 163840
#define WTOT   180224

// -------- scratch (device globals: allocation-free) --------
__device__ float g_bufA[(size_t)NNODE * DD];
__device__ float g_bufB[(size_t)NNODE * DD];
__device__ float g_cat [(size_t)NNODE * KCAT];
__device__ float g_wts [WTOT];
__device__ float g_invdeg[NNODE];
__device__ int   g_deg[NNODE];
__device__ int   g_bsum[1024];
__device__ int   g_offs[NNODE + 1];
__device__ int   g_cursor[NNODE];
__device__ int   g_csr[EE];

// -------- tf32 helpers --------
__device__ __forceinline__ uint32_t f2tf32(float v) {
    uint32_t r;
    asm("cvt.rna.tf32.f32 %0, %1;" : "=r"(r) : "f"(v));
    return r;
}
__device__ __forceinline__ float rtf(float v) { return __uint_as_float(f2tf32(v)); }

__device__ __forceinline__ void mma_tf32(float* c, const uint32_t* a, const uint32_t* b) {
    asm volatile(
        "mma.sync.aligned.m16n8k8.row.col.f32.tf32.tf32.f32 "
        "{%0,%1,%2,%3}, {%4,%5,%6,%7}, {%8,%9}, {%0,%1,%2,%3};"
        : "+f"(c[0]), "+f"(c[1]), "+f"(c[2]), "+f"(c[3])
        : "r"(a[0]), "r"(a[1]), "r"(a[2]), "r"(a[3]), "r"(b[0]), "r"(b[1]));
}

__device__ __forceinline__ void cp16(void* smem_dst, const void* gsrc, bool pred) {
    uint32_t dst = (uint32_t)__cvta_generic_to_shared(smem_dst);
    int sz = pred ? 16 : 0;
    asm volatile("cp.async.ca.shared.global [%0], [%1], 16, %2;\n"
                 :: "r"(dst), "l"(gsrc), "r"(sz));
}
__device__ __forceinline__ void cp_commit() { asm volatile("cp.async.commit_group;\n"); }
__device__ __forceinline__ void cp_wait0()  { asm volatile("cp.async.wait_group 0;\n"); }
__device__ __forceinline__ void cp_wait1()  { asm volatile("cp.async.wait_group 1;\n"); }
__device__ __forceinline__ void cp_wait2()  { asm volatile("cp.async.wait_group 2;\n"); }
__device__ __forceinline__ void cp_wait3()  { asm volatile("cp.async.wait_group 3;\n"); }

// Hs swizzle: row-major [128][128], phys col = col ^ (4*(row&7))  (conflict-free a-frags)
__device__ __forceinline__ int hsw(int r, int c) { return r * 128 + (c ^ ((r & 7) << 2)); }

// -------- utility kernels --------
__global__ void zero_kernel(uint4* __restrict__ p, int n4) {
    int i = blockIdx.x * blockDim.x + threadIdx.x;
    int st = gridDim.x * blockDim.x;
    for (; i < n4; i += st) p[i] = make_uint4(0, 0, 0, 0);
}

__global__ void roundw_kernel(const float* __restrict__ uW, const float* __restrict__ iW,
                              const float* __restrict__ w0, const float* __restrict__ w1,
                              const float* __restrict__ v0, const float* __restrict__ v1) {
    int i = blockIdx.x * blockDim.x + threadIdx.x;
    if (i >= WTOT) return;
    float v;
    if      (i < OFF_I)  v = uW[i - OFF_U];
    else if (i < OFF_W0) v = iW[i - OFF_I];
    else if (i < OFF_W1) v = w0[i - OFF_W0];
    else if (i < OFF_V0) v = w1[i - OFF_W1];
    else if (i < OFF_V1) v = v0[i - OFF_V0];
    else                 v = v1[i - OFF_V1];
    g_wts[i] = rtf(v);
}

__global__ void deg_kernel(const int* __restrict__ dst) {
    int i = blockIdx.x * blockDim.x + threadIdx.x;
    if (i < EE) atomicAdd(&g_deg[dst[i]], 1);
}

__global__ void invdeg_kernel() {
    int i = blockIdx.x * blockDim.x + threadIdx.x;
    if (i < NNODE) g_invdeg[i] = 1.0f / fmaxf((float)g_deg[i], 1.0f);
}

__global__ void scan1_kernel() {
    __shared__ int sm[256];
    int tid = threadIdx.x;
    int i = blockIdx.x * 256 + tid;
    int v = (i < NNODE) ? g_deg[i] : 0;
    sm[tid] = v;
    __syncthreads();
#pragma unroll
    for (int d = 1; d < 256; d <<= 1) {
        int t = (tid >= d) ? sm[tid - d] : 0;
        __syncthreads();
        sm[tid] += t;
        __syncthreads();
    }
    if (i < NNODE) g_offs[i] = sm[tid] - v;
    if (tid == 255) g_bsum[blockIdx.x] = sm[255];
}

__global__ void scan2_kernel() {
    __shared__ int sm[1024];
    int tid = threadIdx.x;
    int v = (tid < NBLK) ? g_bsum[tid] : 0;
    sm[tid] = v;
    __syncthreads();
#pragma unroll
    for (int d = 1; d < 1024; d <<= 1) {
        int t = (tid >= d) ? sm[tid - d] : 0;
        __syncthreads();
        sm[tid] += t;
        __syncthreads();
    }
    g_bsum[tid] = sm[tid] - v;
}

__global__ void scan3_kernel() {
    int i = blockIdx.x * blockDim.x + threadIdx.x;
    if (i < NNODE) {
        int o = g_offs[i] + g_bsum[i >> 8];
        g_offs[i] = o;
        g_cursor[i] = o;
    }
    if (i == 0) g_offs[NNODE] = EE;
}

__global__ void fill_kernel(const int* __restrict__ src, const int* __restrict__ dst) {
    int i = blockIdx.x * blockDim.x + threadIdx.x;
    if (i < EE) {
        int d = dst[i];
        int pos = atomicAdd(&g_cursor[d], 1);
        g_csr[pos] = src[i];
    }
}

// -------- gather aggregation (warp per node), tf32-rounded output --------
__global__ void agg_kernel(const float* __restrict__ x, float* __restrict__ out) {
    int gw   = (blockIdx.x * blockDim.x + threadIdx.x) >> 5;
    int lane = threadIdx.x & 31;
    if (gw >= NNODE) return;
    int off = g_offs[gw];
    int end = g_offs[gw + 1];
    float4 acc = make_float4(0.f, 0.f, 0.f, 0.f);
    for (int j = off; j < end; j++) {
        int s = __ldg(&g_csr[j]);
        float4 v = __ldg((const float4*)(x + (size_t)s * DD) + lane);
        acc.x += v.x; acc.y += v.y; acc.z += v.z; acc.w += v.w;
    }
    float sc = g_invdeg[gw];
    acc.x = rtf(acc.x * sc); acc.y = rtf(acc.y * sc);
    acc.z = rtf(acc.z * sc); acc.w = rtf(acc.w * sc);
    *((float4*)(out + (size_t)gw * DD) + lane) = acc;
}

// -------- embedding gather (vectorized: float4 feat rows, float2 word rows) --------
__global__ void embed_kernel(const int* __restrict__ uf,  const int* __restrict__ itf,
                             const int* __restrict__ ut,  const int* __restrict__ it,
                             const float* __restrict__ ufe, const float* __restrict__ ife,
                             const float* __restrict__ we) {
    int gw   = (blockIdx.x * blockDim.x + threadIdx.x) >> 5;
    int lane = threadIdx.x & 31;
    if (gw >= NNODE) return;
    int n = gw;
    bool user = n < NUSR;
    const int*   f   = user ? uf + (size_t)n * 10 : itf + (size_t)(n - NUSR) * 10;
    const float* tab = user ? ufe : ife;

    float4 a = make_float4(0.f, 0.f, 0.f, 0.f);
#pragma unroll
    for (int j = 0; j < 10; j++) {
        int r = __ldg(f + j);
        float4 v = __ldg((const float4*)(tab + (size_t)r * DD) + lane);
        a.x += v.x; a.y += v.y; a.z += v.z; a.w += v.w;
    }
    float* catrow = g_cat + (size_t)n * KCAT;
    a.x = rtf(a.x * 0.1f); a.y = rtf(a.y * 0.1f);
    a.z = rtf(a.z * 0.1f); a.w = rtf(a.w * 0.1f);
    ((float4*)catrow)[lane] = a;

    const int* t = user ? ut + (size_t)n * 24 : it + (size_t)(n - NUSR) * 24;
#pragma unroll
    for (int fl = 0; fl < 3; fl++) {
        float2 b = make_float2(0.f, 0.f);
#pragma unroll
        for (int w = 0; w < 8; w++) {
            int r = __ldg(t + fl * 8 + w);
            float2 v = __ldg((const float2*)(we + (size_t)r * HALFD) + lane);
            b.x += v.x; b.y += v.y;
        }
        b.x = rtf(b.x * 0.125f); b.y = rtf(b.y * 0.125f);
        ((float2*)(catrow + 128 + fl * 64))[lane] = b;
    }
}

// ======== pipelined TF32 GEMM (projection), BK=32, A dist-2 / W dist-1 ========
// out[M,128] = A[M,K1] @ Wt[K1,128] + bias + addmat  (output tf32-rounded)
// dyn smem: As[3][128][APAD32] | Ws[2][32][WPAD]
__global__ __launch_bounds__(256) void gemm_tf32(
    const float* __restrict__ A,  int K1, int woff,
    const float* __restrict__ bias,
    const float* __restrict__ addmat,
    float* __restrict__ out, int M)
{
    extern __shared__ float sm_[];
    float (*As)[128][APAD32] = (float (*)[128][APAD32])sm_;
    float (*Ws)[32][WPAD]    = (float (*)[32][WPAD])(sm_ + 3 * 128 * APAD32);
    const float* Wt = g_wts + woff;

    int tid  = threadIdx.x;
    int lane = tid & 31;
    int wid  = tid >> 5;
    int wm = wid & 1, wn = wid >> 1;
    int g  = lane >> 2, tg = lane & 3;
    int r0 = blockIdx.x * 128;

    float acc[4][4][4];
#pragma unroll
    for (int mt = 0; mt < 4; mt++)
#pragma unroll
        for (int nt = 0; nt < 4; nt++)
#pragma unroll
            for (int u = 0; u < 4; u++) acc[mt][nt][u] = 0.f;

    int T = K1 / 32;
    auto issueA = [&](int t, int s) {
#pragma unroll
        for (int l = 0; l < 4; l++) {
            int idx = tid + l * 256;
            int m = idx >> 3, c8 = (idx & 7) * 4;
            int row = r0 + m;
            cp16(&As[s][m][c8], A + (size_t)row * K1 + t * 32 + c8, row < M);
        }
        cp_commit();
    };
    auto issueW = [&](int t, int s) {
#pragma unroll
        for (int l = 0; l < 4; l++) {
            int idx = tid + l * 256;
            int k = idx >> 5, n4 = (idx & 31) * 4;
            cp16(&Ws[s][k][n4], Wt + (size_t)(t * 32 + k) * 128 + n4, true);
        }
        cp_commit();
    };

    issueW(0, 0);
    issueA(0, 0);
    issueA(1, 1);
    for (int t = 0; t < T; t++) {
        int sa = t % 3, sw = t & 1;
        if (t + 1 < T) issueW(t + 1, (t + 1) & 1);
        if (t + 2 < T) issueA(t + 2, (t + 2) % 3);
        if (t + 2 < T) cp_wait3();
        else if (t + 1 < T) cp_wait2();
        else cp_wait0();
        __syncthreads();
#pragma unroll
        for (int ks = 0; ks < 32; ks += 8) {
            uint32_t afr[4][4];
#pragma unroll
            for (int mt = 0; mt < 4; mt++) {
                int rb = wm * 64 + mt * 16 + g;
                afr[mt][0] = __float_as_uint(As[sa][rb    ][ks + tg]);
                afr[mt][1] = __float_as_uint(As[sa][rb + 8][ks + tg]);
                afr[mt][2] = __float_as_uint(As[sa][rb    ][ks + tg + 4]);
                afr[mt][3] = __float_as_uint(As[sa][rb + 8][ks + tg + 4]);
            }
            uint32_t bfr[4][2];
#pragma unroll
            for (int nt = 0; nt < 4; nt++) {
                int cb = wn * 32 + nt * 8 + g;
                bfr[nt][0] = __float_as_uint(Ws[sw][ks + tg    ][cb]);
                bfr[nt][1] = __float_as_uint(Ws[sw][ks + tg + 4][cb]);
            }
#pragma unroll
            for (int mt = 0; mt < 4; mt++)
#pragma unroll
                for (int nt = 0; nt < 4; nt++)
                    mma_tf32(acc[mt][nt], afr[mt], bfr[nt]);
        }
        __syncthreads();
    }

#pragma unroll
    for (int mt = 0; mt < 4; mt++) {
#pragma unroll
        for (int nt = 0; nt < 4; nt++) {
            int col = wn * 32 + nt * 8 + tg * 2;
            int rowa = r0 + wm * 64 + mt * 16 + g;
            int rowb = rowa + 8;
            float b0 = bias[col], b1 = bias[col + 1];
            if (rowa < M) {
                float x0 = rtf(acc[mt][nt][0] + b0 + addmat[(size_t)rowa * 128 + col]);
                float x1 = rtf(acc[mt][nt][1] + b1 + addmat[(size_t)rowa * 128 + col + 1]);
                *(float2*)(out + (size_t)rowa * 128 + col) = make_float2(x0, x1);
            }
            if (rowb < M) {
                float x2 = rtf(acc[mt][nt][2] + b0 + addmat[(size_t)rowb * 128 + col]);
                float x3 = rtf(acc[mt][nt][3] + b1 + addmat[(size_t)rowb * 128 + col + 1]);
                *(float2*)(out + (size_t)rowb * 128 + col) = make_float2(x2, x3);
            }
        }
    }
}

// ======== fused SAGE layer: unified 24-tile pipeline, A dist-2 / W dist-1 ========
// tiles 0..7:  h-GEMM  (A=agg, W=vW)      -> acc -> Hs (tf32, relu+bias)
// tiles 8..15: out-GEMM part 1 (A=x, W=wW[0:128])
// tiles 16..23: out-GEMM part 2 (A=Hs smem, W=wW[128:256])
// dyn smem: As[3][128][APAD16] | Ws[2][16][WPAD] | Hs[128*128 swizzled]
template <bool RELU>
__global__ __launch_bounds__(256) void sage_layer(
    const float* __restrict__ agg, const float* __restrict__ x,
    int voff, const float* __restrict__ vb,
    int woff, const float* __restrict__ wb,
    float* __restrict__ out, int M)
{
    extern __shared__ float sm_[];
    float (*As)[128][APAD16] = (float (*)[128][APAD16])sm_;
    float (*Ws)[16][WPAD]    = (float (*)[16][WPAD])(sm_ + 3 * 128 * APAD16);
    float* Hs                = sm_ + 3 * 128 * APAD16 + 2 * 16 * WPAD;
    const float* vW = g_wts + voff;
    const float* wW = g_wts + woff;

    int tid  = threadIdx.x;
    int lane = tid & 31;
    int wid  = tid >> 5;
    int wm = wid & 1, wn = wid >> 1;
    int g  = lane >> 2, tg = lane & 3;
    int r0 = blockIdx.x * 128;

    float acc[4][4][4];
#pragma unroll
    for (int mt = 0; mt < 4; mt++)
#pragma unroll
        for (int nt = 0; nt < 4; nt++)
#pragma unroll
            for (int u = 0; u < 4; u++) acc[mt][nt][u] = 0.f;

    // a-tile at (0..15): 0..7 from agg, 8..15 from x
    auto issueA = [&](int at, int s) {
        const float* Ap = (at < 8) ? agg : x;
        int kt = (at < 8) ? at : at - 8;
#pragma unroll
        for (int l = 0; l < 2; l++) {
            int idx = tid + l * 256;
            int m = idx >> 2, c4 = (idx & 3) * 4;
            int row = r0 + m;
            cp16(&As[s][m][c4], Ap + (size_t)row * DD + kt * 16 + c4, row < M);
        }
        cp_commit();
    };
    // w-tile wt (0..23): 0..7 from vW, 8..23 from wW
    auto issueW = [&](int wt, int s) {
        const float* Wp = (wt < 8) ? (vW + (size_t)wt * 16 * 128)
                                   : (wW + (size_t)(wt - 8) * 16 * 128);
#pragma unroll
        for (int l = 0; l < 2; l++) {
            int idx = tid + l * 256;
            int k = idx >> 5, n4 = (idx & 31) * 4;
            cp16(&Ws[s][k][n4], Wp + (size_t)k * 128 + n4, true);
        }
        cp_commit();
    };

    issueW(0, 0);
    issueA(0, 0);
    issueA(1, 1);

    for (int t = 0; t < 24; t++) {
        int sa = t % 3, sw = t & 1;
        if (t + 1 < 24) issueW(t + 1, (t + 1) & 1);
        if (t + 2 < 16) issueA(t + 2, (t + 2) % 3);
        if (t < 14) cp_wait3();
        else if (t == 14) cp_wait2();
        else if (t < 23) cp_wait1();
        else cp_wait0();
        __syncthreads();

        int hc = (t - 16) * 16;
#pragma unroll
        for (int ks = 0; ks < 16; ks += 8) {
            uint32_t afr[4][4];
#pragma unroll
            for (int mt = 0; mt < 4; mt++) {
                int rb = wm * 64 + mt * 16 + g;
                if (t < 16) {
                    afr[mt][0] = __float_as_uint(As[sa][rb    ][ks + tg]);
                    afr[mt][1] = __float_as_uint(As[sa][rb + 8][ks + tg]);
                    afr[mt][2] = __float_as_uint(As[sa][rb    ][ks + tg + 4]);
                    afr[mt][3] = __float_as_uint(As[sa][rb + 8][ks + tg + 4]);
                } else {
                    afr[mt][0] = __float_as_uint(Hs[hsw(rb,     hc + ks + tg)]);
                    afr[mt][1] = __float_as_uint(Hs[hsw(rb + 8, hc + ks + tg)]);
                    afr[mt][2] = __float_as_uint(Hs[hsw(rb,     hc + ks + tg + 4)]);
                    afr[mt][3] = __float_as_uint(Hs[hsw(rb + 8, hc + ks + tg + 4)]);
                }
            }
            uint32_t bfr[4][2];
#pragma unroll
            for (int nt = 0; nt < 4; nt++) {
                int cb = wn * 32 + nt * 8 + g;
                bfr[nt][0] = __float_as_uint(Ws[sw][ks + tg    ][cb]);
                bfr[nt][1] = __float_as_uint(Ws[sw][ks + tg + 4][cb]);
            }
#pragma unroll
            for (int mt = 0; mt < 4; mt++)
#pragma unroll
                for (int nt = 0; nt < 4; nt++)
                    mma_tf32(acc[mt][nt], afr[mt], bfr[nt]);
        }

        if (t == 7) {
            // phase-1 done: h = relu(acc + vb) -> Hs (tf32), reset acc
#pragma unroll
            for (int mt = 0; mt < 4; mt++) {
#pragma unroll
                for (int nt = 0; nt < 4; nt++) {
                    int col = wn * 32 + nt * 8 + tg * 2;
                    int ra = wm * 64 + mt * 16 + g;
                    float b0 = vb[col], b1 = vb[col + 1];
                    Hs[hsw(ra,     col    )] = rtf(fmaxf(acc[mt][nt][0] + b0, 0.f));
                    Hs[hsw(ra,     col + 1)] = rtf(fmaxf(acc[mt][nt][1] + b1, 0.f));
                    Hs[hsw(ra + 8, col    )] = rtf(fmaxf(acc[mt][nt][2] + b0, 0.f));
                    Hs[hsw(ra + 8, col + 1)] = rtf(fmaxf(acc[mt][nt][3] + b1, 0.f));
#pragma unroll
                    for (int u = 0; u < 4; u++) acc[mt][nt][u] = 0.f;
                }
            }
        }
        __syncthreads();
    }

    // epilogue
#pragma unroll
    for (int mt = 0; mt < 4; mt++) {
#pragma unroll
        for (int nt = 0; nt < 4; nt++) {
            int col = wn * 32 + nt * 8 + tg * 2;
            int rowa = r0 + wm * 64 + mt * 16 + g;
            int rowb = rowa + 8;
            float b0 = wb[col], b1 = wb[col + 1];
            if (rowa < M) {
                float x0 = acc[mt][nt][0] + b0;
                float x1 = acc[mt][nt][1] + b1;
                if (RELU) { x0 = rtf(fmaxf(x0, 0.f)); x1 = rtf(fmaxf(x1, 0.f)); }
                *(float2*)(out + (size_t)rowa * 128 + col) = make_float2(x0, x1);
            }
            if (rowb < M) {
                float x2 = acc[mt][nt][2] + b0;
                float x3 = acc[mt][nt][3] + b1;
                if (RELU) { x2 = rtf(fmaxf(x2, 0.f)); x3 = rtf(fmaxf(x3, 0.f)); }
                *(float2*)(out + (size_t)rowb * 128 + col) = make_float2(x2, x3);
            }
        }
    }
}

// -------- launch --------
extern "C" void kernel_launch(void* const* d_in, const int* in_sizes, int n_in,
                              void* d_out, int out_size) {
    const int*   edge          = (const int*)d_in[0];
    const int*   src           = edge;
    const int*   dstp          = edge + EE;
    const int*   user_features = (const int*)d_in[1];
    const int*   item_features = (const int*)d_in[2];
    const int*   user_text     = (const int*)d_in[3];
    const int*   item_text     = (const int*)d_in[4];
    const float* user_id_emb   = (const float*)d_in[5];
    const float* item_id_emb   = (const float*)d_in[6];
    const float* user_feat_emb = (const float*)d_in[7];
    const float* item_feat_emb = (const float*)d_in[8];
    const float* word_emb      = (const float*)d_in[9];
    const float* user_projW    = (const float*)d_in[10];
    const float* user_projb    = (const float*)d_in[11];
    const float* item_projW    = (const float*)d_in[12];
    const float* item_projb    = (const float*)d_in[13];
    const float* w0W = (const float*)d_in[14];
    const float* w0b = (const float*)d_in[15];
    const float* w1W = (const float*)d_in[16];
    const float* w1b = (const float*)d_in[17];
    const float* v0W = (const float*)d_in[18];
    const float* v0b = (const float*)d_in[19];
    const float* v1W = (const float*)d_in[20];
    const float* v1b = (const float*)d_in[21];

    float *pA, *pB, *pcat;
    int   *pdeg;
    cudaGetSymbolAddress((void**)&pA,   g_bufA);
    cudaGetSymbolAddress((void**)&pB,   g_bufB);
    cudaGetSymbolAddress((void**)&pcat, g_cat);
    cudaGetSymbolAddress((void**)&pdeg, g_deg);

    const int GEMM_SMEM = (3 * 128 * APAD32 + 2 * 32 * WPAD) * 4;               // 90112
    const int SAGE_SMEM = (3 * 128 * APAD16 + 2 * 16 * WPAD + 128 * 128) * 4;   // 113664
    cudaFuncSetAttribute(gemm_tf32, cudaFuncAttributeMaxDynamicSharedMemorySize, GEMM_SMEM);
    cudaFuncSetAttribute(sage_layer<true>,  cudaFuncAttributeMaxDynamicSharedMemorySize, SAGE_SMEM);
    cudaFuncSetAttribute(sage_layer<false>, cudaFuncAttributeMaxDynamicSharedMemorySize, SAGE_SMEM);

    // order: launch index 3 = user projection GEMM (profiler slot)
    zero_kernel<<<64, 256>>>((uint4*)pdeg, NNODE / 4);                       // 0
    embed_kernel<<<(NNODE * 32 + 255) / 256, 256>>>(                         // 1
        user_features, item_features, user_text, item_text,
        user_feat_emb, item_feat_emb, word_emb);
    roundw_kernel<<<(WTOT + 255) / 256, 256>>>(user_projW, item_projW,       // 2
                                               w0W, w1W, v0W, v1W);
    gemm_tf32<<<(NUSR + 127) / 128, 256, GEMM_SMEM>>>(                       // 3 (profiled)
        pcat, KCAT, OFF_U, user_projb, user_id_emb, pA, NUSR);
    gemm_tf32<<<(NITM + 127) / 128, 256, GEMM_SMEM>>>(                       // 4
        pcat + (size_t)NUSR * KCAT, KCAT, OFF_I, item_projb, item_id_emb,
        pA + (size_t)NUSR * DD, NITM);
    deg_kernel<<<(EE + 255) / 256, 256>>>(dstp);                             // 5
    invdeg_kernel<<<(NNODE + 255) / 256, 256>>>();                           // 6
    scan1_kernel<<<NBLK, 256>>>();                                           // 7
    scan2_kernel<<<1, 1024>>>();                                             // 8
    scan3_kernel<<<(NNODE + 255) / 256, 256>>>();                            // 9
    fill_kernel<<<(EE + 255) / 256, 256>>>(src, dstp);                       // 10

    // ----- layer 0 -----
    agg_kernel<<<(NNODE * 32 + 255) / 256, 256>>>(pA, pB);                   // 11
    sage_layer<true><<<(NNODE + 127) / 128, 256, SAGE_SMEM>>>(               // 12
        pB, pA, OFF_V0, v0b, OFF_W0, w0b, pcat, NNODE);

    // ----- layer 1 -----
    agg_kernel<<<(NNODE * 32 + 255) / 256, 256>>>(pcat, pA);                 // 13
    sage_layer<false><<<(NNODE + 127) / 128, 256, SAGE_SMEM>>>(              // 14
        pA, pcat, OFF_V1, v1b, OFF_W1, w1b, (float*)d_out, NNODE);
}